// round 1
// baseline (speedup 1.0000x reference)
#include <cuda_runtime.h>
#include <cuda_bf16.h>
#include <cstdint>

// Problem constants (shapes fixed by the dataset)
#define NMAX 100000
#define EMAX 1700000   // E (1.6M) + N self-loops (100k)
#define EPS 1e-5f

// -------- scratch (static device globals; no allocation allowed) --------
__device__ float g_h[(size_t)NMAX * 128];    // GEMM output (h), reused for layer 1
__device__ float g_agg[(size_t)NMAX * 128];  // layer-0 aggregation / BN+ReLU output
__device__ float g_s[NMAX];
__device__ float g_d[NMAX];
__device__ float g_m[NMAX];                  // segment max (int-ordered float bits)
__device__ float g_den[NMAX];                // segment sum of exp
__device__ float g_w[EMAX];                  // per-edge logit, then exp weight
__device__ float g_sum[128];                 // BN column sums
__device__ float g_sq[128];                  // BN column sum-of-squares

// ------------------------------- SGEMM ----------------------------------
// C[M,Nn] = A[M,K] @ B[K,Nn], all row-major fp32.
template <int BM, int BN, int BK, int TM, int TN>
__global__ void sgemm_kernel(int M, int K, int Nn,
                             const float* __restrict__ A,
                             const float* __restrict__ B,
                             float* __restrict__ C) {
    __shared__ float As[BK][BM];
    __shared__ float Bs[BK][BN];
    constexpr int TCOLS = BN / TN;
    constexpr int NTHREADS = (BM / TM) * (BN / TN);
    const int tid = threadIdx.x;
    const int tx = tid % TCOLS;
    const int ty = tid / TCOLS;
    const int rowBase = blockIdx.y * BM;
    const int colBase = blockIdx.x * BN;

    float acc[TM][TN];
#pragma unroll
    for (int i = 0; i < TM; i++)
#pragma unroll
        for (int j = 0; j < TN; j++) acc[i][j] = 0.f;

    for (int k0 = 0; k0 < K; k0 += BK) {
        // A tile (BM x BK) -> transposed into As[kk][m]
#pragma unroll
        for (int i = tid; i < BM * BK; i += NTHREADS) {
            int m = i / BK, kk = i % BK;
            int gr = rowBase + m;
            As[kk][m] = (gr < M) ? A[(size_t)gr * K + k0 + kk] : 0.f;
        }
        // B tile (BK x BN)
#pragma unroll
        for (int i = tid; i < BK * BN; i += NTHREADS) {
            int kk = i / BN, nn = i % BN;
            Bs[kk][nn] = B[(size_t)(k0 + kk) * Nn + colBase + nn];
        }
        __syncthreads();
#pragma unroll
        for (int kk = 0; kk < BK; kk++) {
            float ar[TM], br[TN];
#pragma unroll
            for (int i = 0; i < TM; i++) ar[i] = As[kk][ty * TM + i];
#pragma unroll
            for (int j = 0; j < TN; j++) br[j] = Bs[kk][tx * TN + j];
#pragma unroll
            for (int i = 0; i < TM; i++)
#pragma unroll
                for (int j = 0; j < TN; j++) acc[i][j] += ar[i] * br[j];
        }
        __syncthreads();
    }
#pragma unroll
    for (int i = 0; i < TM; i++) {
        int gr = rowBase + ty * TM + i;
        if (gr >= M) continue;
#pragma unroll
        for (int j = 0; j < TN; j++)
            C[(size_t)gr * Nn + colBase + tx * TN + j] = acc[i][j];
    }
}

// -------------------- per-node alpha_src / alpha_dst ---------------------
__global__ void sd_kernel(int n, int D, const float* __restrict__ Hm,
                          const float* __restrict__ a_s,
                          const float* __restrict__ a_d,
                          float* __restrict__ so, float* __restrict__ dout) {
    int w = (blockIdx.x * blockDim.x + threadIdx.x) >> 5;
    int lane = threadIdx.x & 31;
    if (w >= n) return;
    float s = 0.f, d = 0.f;
    for (int j = lane; j < D; j += 32) {
        float hv = Hm[(size_t)w * D + j];
        s += hv * a_s[j];
        d += hv * a_d[j];
    }
#pragma unroll
    for (int o = 16; o; o >>= 1) {
        s += __shfl_xor_sync(0xFFFFFFFFu, s, o);
        d += __shfl_xor_sync(0xFFFFFFFFu, d, o);
    }
    if (lane == 0) { so[w] = s; dout[w] = d; }
}

// ------------------------ edge pass 1: logit + max -----------------------
__global__ void edge_logit_kernel(int E_, int n, const int* __restrict__ ei,
                                  const float* __restrict__ s,
                                  const float* __restrict__ d,
                                  float* __restrict__ logit,
                                  float* __restrict__ mmax) {
    int e = blockIdx.x * blockDim.x + threadIdx.x;
    int tot = E_ + n;
    if (e >= tot) return;
    int src, dst;
    if (e < E_) { src = ei[e]; dst = ei[E_ + e]; }
    else        { src = dst = e - E_; }
    float lg = s[src] + d[dst];
    lg = lg > 0.f ? lg : 0.2f * lg;   // LeakyReLU(0.2)
    logit[e] = lg;
    // float max via integer-ordered atomics (init bits = 0xFFFFFFFF acts as -inf)
    if (lg >= 0.f)
        atomicMax((int*)&mmax[dst], __float_as_int(lg));
    else
        atomicMin((unsigned int*)&mmax[dst], __float_as_uint(lg));
}

// ---------------------- edge pass 2: exp + denom sum ---------------------
__global__ void edge_exp_kernel(int E_, int n, const int* __restrict__ ei,
                                const float* __restrict__ mmax,
                                float* __restrict__ logit,
                                float* __restrict__ den) {
    int e = blockIdx.x * blockDim.x + threadIdx.x;
    int tot = E_ + n;
    if (e >= tot) return;
    int dst = (e < E_) ? ei[E_ + e] : (e - E_);
    float w = __expf(logit[e] - mmax[dst]);
    logit[e] = w;
    atomicAdd(&den[dst], w);
}

// ---------------------- edge pass 3: feature scatter ---------------------
template <int D>
__global__ void edge_scatter_kernel(int E_, int n, const int* __restrict__ ei,
                                    const float* __restrict__ w,
                                    const float* __restrict__ den,
                                    const float* __restrict__ Hm,
                                    float* __restrict__ out) {
    constexpr int LANES = D / 4;  // float4 lanes per edge
    int idx = blockIdx.x * blockDim.x + threadIdx.x;
    int e = idx / LANES;
    int lane = idx % LANES;
    int tot = E_ + n;
    if (e >= tot) return;
    int src, dst;
    if (e < E_) { src = ei[e]; dst = ei[E_ + e]; }
    else        { src = dst = e - E_; }
    float coef = w[e] / den[dst];
    const float4* hs = (const float4*)(Hm + (size_t)src * D);
    float4* op = (float4*)(out + (size_t)dst * D);
    float4 v = hs[lane];
    v.x *= coef; v.y *= coef; v.z *= coef; v.w *= coef;
    asm volatile("red.global.add.v4.f32 [%0], {%1, %2, %3, %4};"
                 :: "l"(op + lane), "f"(v.x), "f"(v.y), "f"(v.z), "f"(v.w)
                 : "memory");
}

// ---------------------------- BatchNorm ----------------------------------
template <int D>
__global__ void bn_stats_kernel(int n, const float* __restrict__ x,
                                float* __restrict__ sum, float* __restrict__ sq) {
    int c = threadIdx.x;          // blockDim.x == D
    int r0 = blockIdx.x * 64;
    int r1 = min(r0 + 64, n);
    float s = 0.f, q = 0.f;
    for (int r = r0; r < r1; r++) {
        float v = x[(size_t)r * D + c];
        s += v;
        q += v * v;
    }
    atomicAdd(&sum[c], s);
    atomicAdd(&sq[c], q);
}

template <int D>
__global__ void bn_relu_kernel(int n, float* __restrict__ x,
                               const float* __restrict__ sum,
                               const float* __restrict__ sq,
                               const float* __restrict__ g,
                               const float* __restrict__ b) {
    int i = blockIdx.x * blockDim.x + threadIdx.x;
    if (i >= n * D) return;
    int c = i % D;
    float invn = 1.f / (float)n;
    float mu = sum[c] * invn;
    float var = sq[c] * invn - mu * mu;
    float v = (x[i] - mu) * rsqrtf(var + EPS) * g[c] + b[c];
    x[i] = fmaxf(v, 0.f);
}

// ------------------------------ launcher ---------------------------------
extern "C" void kernel_launch(void* const* d_in, const int* in_sizes, int n_in,
                              void* d_out, int out_size) {
    const float* x   = (const float*)d_in[0];
    const int*   ei  = (const int*)d_in[1];
    const float* W0  = (const float*)d_in[2];
    const float* as0 = (const float*)d_in[3];
    const float* ad0 = (const float*)d_in[4];
    const float* gg0 = (const float*)d_in[5];
    const float* bb0 = (const float*)d_in[6];
    const float* W1  = (const float*)d_in[7];
    const float* as1 = (const float*)d_in[8];
    const float* ad1 = (const float*)d_in[9];
    const float* gg1 = (const float*)d_in[10];
    const float* bb1 = (const float*)d_in[11];

    const int F = 128, Hd = 128, C = 64;
    const int n  = in_sizes[0] / F;
    const int E_ = in_sizes[1] / 2;
    const int tot = E_ + n;
    float* out = (float*)d_out;

    float *hbuf, *abuf, *sbuf, *dbuf, *mbuf, *denbuf, *wbuf, *sumb, *sqb;
    cudaGetSymbolAddress((void**)&hbuf, g_h);
    cudaGetSymbolAddress((void**)&abuf, g_agg);
    cudaGetSymbolAddress((void**)&sbuf, g_s);
    cudaGetSymbolAddress((void**)&dbuf, g_d);
    cudaGetSymbolAddress((void**)&mbuf, g_m);
    cudaGetSymbolAddress((void**)&denbuf, g_den);
    cudaGetSymbolAddress((void**)&wbuf, g_w);
    cudaGetSymbolAddress((void**)&sumb, g_sum);
    cudaGetSymbolAddress((void**)&sqb, g_sq);

    // ============================ Layer 0 ============================
    {
        dim3 grid((Hd + 127) / 128, (n + 63) / 64);
        sgemm_kernel<64, 128, 8, 4, 8><<<grid, 256>>>(n, F, Hd, x, W0, hbuf);
    }
    sd_kernel<<<(n * 32 + 255) / 256, 256>>>(n, Hd, hbuf, as0, ad0, sbuf, dbuf);

    cudaMemsetAsync(mbuf, 0xFF, (size_t)n * sizeof(float));          // -inf in int ordering
    cudaMemsetAsync(denbuf, 0, (size_t)n * sizeof(float));
    cudaMemsetAsync(abuf, 0, (size_t)n * Hd * sizeof(float));

    edge_logit_kernel<<<(tot + 255) / 256, 256>>>(E_, n, ei, sbuf, dbuf, wbuf, mbuf);
    edge_exp_kernel<<<(tot + 255) / 256, 256>>>(E_, n, ei, mbuf, wbuf, denbuf);
    {
        long long threads = (long long)tot * (Hd / 4);
        edge_scatter_kernel<128><<<(unsigned)((threads + 255) / 256), 256>>>(
            E_, n, ei, wbuf, denbuf, hbuf, abuf);
    }

    cudaMemsetAsync(sumb, 0, 128 * sizeof(float));
    cudaMemsetAsync(sqb, 0, 128 * sizeof(float));
    bn_stats_kernel<128><<<(n + 63) / 64, 128>>>(n, abuf, sumb, sqb);
    bn_relu_kernel<128><<<((long long)n * Hd + 255) / 256, 256>>>(n, abuf, sumb, sqb, gg0, bb0);

    // ============================ Layer 1 ============================
    {
        dim3 grid((C + 63) / 64, (n + 63) / 64);
        sgemm_kernel<64, 64, 8, 4, 4><<<grid, 256>>>(n, Hd, C, abuf, W1, hbuf);
    }
    sd_kernel<<<(n * 32 + 255) / 256, 256>>>(n, C, hbuf, as1, ad1, sbuf, dbuf);

    cudaMemsetAsync(mbuf, 0xFF, (size_t)n * sizeof(float));
    cudaMemsetAsync(denbuf, 0, (size_t)n * sizeof(float));
    cudaMemsetAsync(out, 0, (size_t)n * C * sizeof(float));

    edge_logit_kernel<<<(tot + 255) / 256, 256>>>(E_, n, ei, sbuf, dbuf, wbuf, mbuf);
    edge_exp_kernel<<<(tot + 255) / 256, 256>>>(E_, n, ei, mbuf, wbuf, denbuf);
    {
        long long threads = (long long)tot * (C / 4);
        edge_scatter_kernel<64><<<(unsigned)((threads + 255) / 256), 256>>>(
            E_, n, ei, wbuf, denbuf, hbuf, out);
    }

    cudaMemsetAsync(sumb, 0, 128 * sizeof(float));
    cudaMemsetAsync(sqb, 0, 128 * sizeof(float));
    bn_stats_kernel<64><<<(n + 63) / 64, 64>>>(n, out, sumb, sqb);
    bn_relu_kernel<64><<<((long long)n * C + 255) / 256, 256>>>(n, out, sumb, sqb, gg1, bb1);
}

// round 2
// speedup vs baseline: 1.4205x; 1.4205x over previous
#include <cuda_runtime.h>
#include <cuda_bf16.h>
#include <cstdint>

#define NMAX 100000
#define EMAX 1700000   // E (1.6M) + N self-loops (100k)
#define EPS 1e-5f

// -------- scratch (static device globals; no allocation allowed) --------
__device__ float g_h[(size_t)NMAX * 128];    // GEMM output (h), reused for layer 1
__device__ float g_agg[(size_t)NMAX * 128];  // layer-0 aggregation / BN+ReLU output
__device__ float g_s[NMAX];
__device__ float g_d[NMAX];
__device__ int   g_deg[NMAX];                // per-dst degree (histogram)
__device__ int   g_rowptr[NMAX + 1];         // CSR row pointers
__device__ int   g_cursor[NMAX];             // fill cursors
__device__ int   g_csrc[EMAX];               // CSR-ordered src node ids
__device__ int   g_bsums[256];               // scan block sums
__device__ float g_sum[128];                 // BN column sums
__device__ float g_sq[128];                  // BN column sum-of-squares

// ------------------------------- SGEMM ----------------------------------
template <int BM, int BN, int BK, int TM, int TN>
__global__ void sgemm_kernel(int M, int K, int Nn,
                             const float* __restrict__ A,
                             const float* __restrict__ B,
                             float* __restrict__ C) {
    __shared__ float As[BK][BM];
    __shared__ float Bs[BK][BN];
    constexpr int TCOLS = BN / TN;
    constexpr int NTHREADS = (BM / TM) * (BN / TN);
    const int tid = threadIdx.x;
    const int tx = tid % TCOLS;
    const int ty = tid / TCOLS;
    const int rowBase = blockIdx.y * BM;
    const int colBase = blockIdx.x * BN;

    float acc[TM][TN];
#pragma unroll
    for (int i = 0; i < TM; i++)
#pragma unroll
        for (int j = 0; j < TN; j++) acc[i][j] = 0.f;

    for (int k0 = 0; k0 < K; k0 += BK) {
#pragma unroll
        for (int i = tid; i < BM * BK; i += NTHREADS) {
            int m = i / BK, kk = i % BK;
            int gr = rowBase + m;
            As[kk][m] = (gr < M) ? A[(size_t)gr * K + k0 + kk] : 0.f;
        }
#pragma unroll
        for (int i = tid; i < BK * BN; i += NTHREADS) {
            int kk = i / BN, nn = i % BN;
            Bs[kk][nn] = B[(size_t)(k0 + kk) * Nn + colBase + nn];
        }
        __syncthreads();
#pragma unroll
        for (int kk = 0; kk < BK; kk++) {
            float ar[TM], br[TN];
#pragma unroll
            for (int i = 0; i < TM; i++) ar[i] = As[kk][ty * TM + i];
#pragma unroll
            for (int j = 0; j < TN; j++) br[j] = Bs[kk][tx * TN + j];
#pragma unroll
            for (int i = 0; i < TM; i++)
#pragma unroll
                for (int j = 0; j < TN; j++) acc[i][j] += ar[i] * br[j];
        }
        __syncthreads();
    }
#pragma unroll
    for (int i = 0; i < TM; i++) {
        int gr = rowBase + ty * TM + i;
        if (gr >= M) continue;
#pragma unroll
        for (int j = 0; j < TN; j++)
            C[(size_t)gr * Nn + colBase + tx * TN + j] = acc[i][j];
    }
}

// -------------------- per-node alpha_src / alpha_dst ---------------------
__global__ void sd_kernel(int n, int D, const float* __restrict__ Hm,
                          const float* __restrict__ a_s,
                          const float* __restrict__ a_d,
                          float* __restrict__ so, float* __restrict__ dout) {
    int w = (blockIdx.x * blockDim.x + threadIdx.x) >> 5;
    int lane = threadIdx.x & 31;
    if (w >= n) return;
    float s = 0.f, d = 0.f;
    for (int j = lane; j < D; j += 32) {
        float hv = Hm[(size_t)w * D + j];
        s += hv * a_s[j];
        d += hv * a_d[j];
    }
#pragma unroll
    for (int o = 16; o; o >>= 1) {
        s += __shfl_xor_sync(0xFFFFFFFFu, s, o);
        d += __shfl_xor_sync(0xFFFFFFFFu, d, o);
    }
    if (lane == 0) { so[w] = s; dout[w] = d; }
}

// ------------------------------ CSR build --------------------------------
__global__ void hist_kernel(int E_, int n, const int* __restrict__ ei,
                            int* __restrict__ deg) {
    int e = blockIdx.x * blockDim.x + threadIdx.x;
    int tot = E_ + n;
    if (e >= tot) return;
    int dst = (e < E_) ? ei[E_ + e] : (e - E_);
    atomicAdd(&deg[dst], 1);
}

// Block-wise exclusive scan: 256 threads x 4 elems = 1024 per block.
__global__ void scan1_kernel(const int* __restrict__ deg, int* __restrict__ excl,
                             int* __restrict__ bsums, int n) {
    __shared__ int sh[256];
    int tid = threadIdx.x;
    int base = blockIdx.x * 1024 + tid * 4;
    int v[4];
#pragma unroll
    for (int j = 0; j < 4; j++) v[j] = (base + j < n) ? deg[base + j] : 0;
    int tsum = v[0] + v[1] + v[2] + v[3];
    sh[tid] = tsum;
    __syncthreads();
    // Hillis-Steele inclusive scan on thread totals
    for (int off = 1; off < 256; off <<= 1) {
        int t = (tid >= off) ? sh[tid - off] : 0;
        __syncthreads();
        sh[tid] += t;
        __syncthreads();
    }
    int run = sh[tid] - tsum;   // exclusive prefix for this thread
#pragma unroll
    for (int j = 0; j < 4; j++) {
        if (base + j < n) excl[base + j] = run;
        run += v[j];
    }
    if (tid == 255) bsums[blockIdx.x] = sh[255];
}

__global__ void scan2_kernel(int* __restrict__ bsums, int nb) {
    if (threadIdx.x == 0 && blockIdx.x == 0) {
        int acc = 0;
        for (int i = 0; i < nb; i++) { int t = bsums[i]; bsums[i] = acc; acc += t; }
    }
}

__global__ void scan3_kernel(int* __restrict__ rowptr, const int* __restrict__ bsums,
                             int n, int tot) {
    int i = blockIdx.x * blockDim.x + threadIdx.x;
    if (i < n) rowptr[i] += bsums[i >> 10];
    if (i == 0) rowptr[n] = tot;
}

__global__ void fill_kernel(int E_, int n, const int* __restrict__ ei,
                            int* __restrict__ cursor, int* __restrict__ csrc) {
    int e = blockIdx.x * blockDim.x + threadIdx.x;
    int tot = E_ + n;
    if (e >= tot) return;
    int src, dst;
    if (e < E_) { src = ei[e]; dst = ei[E_ + e]; }
    else        { src = dst = e - E_; }
    int pos = atomicAdd(&cursor[dst], 1);
    csrc[pos] = src;
}

// ---------------- fused per-dst softmax + feature aggregation ------------
// One warp per dst node. Online softmax (max+denominator in one pass), then
// chunked feature gather with shfl-broadcast coefficients. No atomics.
template <int D>
__global__ void gat_agg_kernel(int n, const int* __restrict__ rowptr,
                               const int* __restrict__ csrc,
                               const float* __restrict__ s,
                               const float* __restrict__ dd,
                               const float* __restrict__ Hm,
                               float* __restrict__ out) {
    constexpr int V = D / 32;   // floats per lane (4 for D=128, 2 for D=64)
    int w = (blockIdx.x * blockDim.x + threadIdx.x) >> 5;
    int lane = threadIdx.x & 31;
    if (w >= n) return;
    int start = rowptr[w];
    int end = rowptr[w + 1];
    float dv = dd[w];

    // online softmax: per-lane running (max, scaled sum)
    float m = -1e30f, den = 0.f;
    for (int i = start + lane; i < end; i += 32) {
        float lg = s[csrc[i]] + dv;
        lg = lg > 0.f ? lg : 0.2f * lg;
        if (lg > m) { den = den * __expf(m - lg) + 1.f; m = lg; }
        else        { den += __expf(lg - m); }
    }
    // warp merge of (m, den)
#pragma unroll
    for (int o = 16; o; o >>= 1) {
        float mo = __shfl_xor_sync(0xFFFFFFFFu, m, o);
        float do_ = __shfl_xor_sync(0xFFFFFFFFu, den, o);
        float mn = fmaxf(m, mo);
        den = den * __expf(m - mn) + do_ * __expf(mo - mn);
        m = mn;
    }
    float inv = 1.f / den;

    float acc[V];
#pragma unroll
    for (int j = 0; j < V; j++) acc[j] = 0.f;

    for (int base = start; base < end; base += 32) {
        int i = base + lane;
        int srcv = 0;
        float wv = 0.f;
        if (i < end) {
            srcv = csrc[i];
            float lg = s[srcv] + dv;
            lg = lg > 0.f ? lg : 0.2f * lg;
            wv = __expf(lg - m) * inv;
        }
        int cnt = min(32, end - base);
        for (int k = 0; k < cnt; k++) {
            float c = __shfl_sync(0xFFFFFFFFu, wv, k);
            int sc = __shfl_sync(0xFFFFFFFFu, srcv, k);
            if (V == 4) {
                float4 v = ((const float4*)(Hm + (size_t)sc * D))[lane];
                acc[0] += c * v.x; acc[1] += c * v.y;
                acc[2] += c * v.z; acc[3] += c * v.w;
            } else {
                float2 v = ((const float2*)(Hm + (size_t)sc * D))[lane];
                acc[0] += c * v.x; acc[1] += c * v.y;
            }
        }
    }
    if (V == 4) {
        ((float4*)(out + (size_t)w * D))[lane] =
            make_float4(acc[0], acc[1], acc[2], acc[3]);
    } else {
        ((float2*)(out + (size_t)w * D))[lane] = make_float2(acc[0], acc[1]);
    }
}

// ---------------------------- BatchNorm ----------------------------------
template <int D>
__global__ void bn_stats_kernel(int n, const float* __restrict__ x,
                                float* __restrict__ sum, float* __restrict__ sq) {
    int c = threadIdx.x;          // blockDim.x == D
    int r0 = blockIdx.x * 64;
    int r1 = min(r0 + 64, n);
    float s = 0.f, q = 0.f;
    for (int r = r0; r < r1; r++) {
        float v = x[(size_t)r * D + c];
        s += v;
        q += v * v;
    }
    atomicAdd(&sum[c], s);
    atomicAdd(&sq[c], q);
}

template <int D>
__global__ void bn_relu_kernel(int n, float* __restrict__ x,
                               const float* __restrict__ sum,
                               const float* __restrict__ sq,
                               const float* __restrict__ g,
                               const float* __restrict__ b) {
    int i = blockIdx.x * blockDim.x + threadIdx.x;
    if (i >= n * D) return;
    int c = i % D;
    float invn = 1.f / (float)n;
    float mu = sum[c] * invn;
    float var = sq[c] * invn - mu * mu;
    float v = (x[i] - mu) * rsqrtf(var + EPS) * g[c] + b[c];
    x[i] = fmaxf(v, 0.f);
}

// ------------------------------ launcher ---------------------------------
extern "C" void kernel_launch(void* const* d_in, const int* in_sizes, int n_in,
                              void* d_out, int out_size) {
    const float* x   = (const float*)d_in[0];
    const int*   ei  = (const int*)d_in[1];
    const float* W0  = (const float*)d_in[2];
    const float* as0 = (const float*)d_in[3];
    const float* ad0 = (const float*)d_in[4];
    const float* gg0 = (const float*)d_in[5];
    const float* bb0 = (const float*)d_in[6];
    const float* W1  = (const float*)d_in[7];
    const float* as1 = (const float*)d_in[8];
    const float* ad1 = (const float*)d_in[9];
    const float* gg1 = (const float*)d_in[10];
    const float* bb1 = (const float*)d_in[11];

    const int F = 128, Hd = 128, C = 64;
    const int n  = in_sizes[0] / F;
    const int E_ = in_sizes[1] / 2;
    const int tot = E_ + n;
    float* out = (float*)d_out;

    float *hbuf, *abuf, *sbuf, *dbuf, *sumb, *sqb;
    int *degb, *rowp, *curs, *csrc, *bsums;
    cudaGetSymbolAddress((void**)&hbuf, g_h);
    cudaGetSymbolAddress((void**)&abuf, g_agg);
    cudaGetSymbolAddress((void**)&sbuf, g_s);
    cudaGetSymbolAddress((void**)&dbuf, g_d);
    cudaGetSymbolAddress((void**)&sumb, g_sum);
    cudaGetSymbolAddress((void**)&sqb, g_sq);
    cudaGetSymbolAddress((void**)&degb, g_deg);
    cudaGetSymbolAddress((void**)&rowp, g_rowptr);
    cudaGetSymbolAddress((void**)&curs, g_cursor);
    cudaGetSymbolAddress((void**)&csrc, g_csrc);
    cudaGetSymbolAddress((void**)&bsums, g_bsums);

    // ======================= CSR build (shared by both layers) ============
    cudaMemsetAsync(degb, 0, (size_t)n * sizeof(int));
    hist_kernel<<<(tot + 255) / 256, 256>>>(E_, n, ei, degb);
    int nb = (n + 1023) / 1024;
    scan1_kernel<<<nb, 256>>>(degb, rowp, bsums, n);
    scan2_kernel<<<1, 32>>>(bsums, nb);
    scan3_kernel<<<(n + 255) / 256, 256>>>(rowp, bsums, n, tot);
    cudaMemcpyAsync(curs, rowp, (size_t)n * sizeof(int), cudaMemcpyDeviceToDevice);
    fill_kernel<<<(tot + 255) / 256, 256>>>(E_, n, ei, curs, csrc);

    // ============================ Layer 0 =================================
    {
        dim3 grid(1, (n + 63) / 64);
        sgemm_kernel<64, 128, 8, 4, 8><<<grid, 256>>>(n, F, Hd, x, W0, hbuf);
    }
    sd_kernel<<<(n * 32 + 255) / 256, 256>>>(n, Hd, hbuf, as0, ad0, sbuf, dbuf);
    gat_agg_kernel<128><<<(n * 32 + 255) / 256, 256>>>(n, rowp, csrc, sbuf, dbuf, hbuf, abuf);

    cudaMemsetAsync(sumb, 0, 128 * sizeof(float));
    cudaMemsetAsync(sqb, 0, 128 * sizeof(float));
    bn_stats_kernel<128><<<(n + 63) / 64, 128>>>(n, abuf, sumb, sqb);
    bn_relu_kernel<128><<<((long long)n * Hd + 255) / 256, 256>>>(n, abuf, sumb, sqb, gg0, bb0);

    // ============================ Layer 1 =================================
    {
        dim3 grid(1, (n + 63) / 64);
        sgemm_kernel<64, 64, 8, 4, 4><<<grid, 256>>>(n, Hd, C, abuf, W1, hbuf);
    }
    sd_kernel<<<(n * 32 + 255) / 256, 256>>>(n, C, hbuf, as1, ad1, sbuf, dbuf);
    gat_agg_kernel<64><<<(n * 32 + 255) / 256, 256>>>(n, rowp, csrc, sbuf, dbuf, hbuf, out);

    cudaMemsetAsync(sumb, 0, 128 * sizeof(float));
    cudaMemsetAsync(sqb, 0, 128 * sizeof(float));
    bn_stats_kernel<64><<<(n + 63) / 64, 64>>>(n, out, sumb, sqb);
    bn_relu_kernel<64><<<((long long)n * C + 255) / 256, 256>>>(n, out, sumb, sqb, gg1, bb1);
}

// round 3
// speedup vs baseline: 2.0940x; 1.4741x over previous
#include <cuda_runtime.h>
#include <cuda_bf16.h>
#include <cstdint>

#define NMAX 100000
#define EMAX 1700000   // E (1.6M) + N self-loops (100k)
#define EPS 1e-5f

// -------- scratch (static device globals; no allocation allowed) --------
__device__ float g_h[(size_t)NMAX * 128];    // GEMM output (h) per layer
__device__ float g_agg[(size_t)NMAX * 128];  // layer-0 aggregation (pre-BN)
__device__ float g_s[NMAX];
__device__ float g_d[NMAX];
__device__ int   g_deg[NMAX];
__device__ int   g_rowptr[NMAX + 1];
__device__ int   g_cursor[NMAX];
__device__ int   g_csrc[EMAX];
__device__ int   g_bsums[256];
__device__ float g_stats[256];               // [0:128) col sums, [128:256) col sumsq
__device__ float g_scale[128];
__device__ float g_shift[128];

// ------------------------------- SGEMM ----------------------------------
// C[M,N] = A'[M,K] @ B[K,N]; BN == N (single block column). Optionally the A
// elements are transformed on load: a = max(0, a*scale[k] + shift[k]) (fused
// BatchNorm+ReLU of the previous layer). Fused epilogue computes per-row dot
// products s = C·a_s, d = C·a_d.
// BM=128, BK=16, 256 threads, TM=8, TN=BN/16.
template <int BN, bool TRANSFORM>
__global__ __launch_bounds__(256) void sgemm_fused_kernel(
    int M, int K,
    const float* __restrict__ A,
    const float* __restrict__ B,
    float* __restrict__ C,
    const float* __restrict__ a_s,
    const float* __restrict__ a_d,
    float* __restrict__ so, float* __restrict__ dout,
    const float* __restrict__ scale,
    const float* __restrict__ shift) {
    constexpr int BM = 128, BK = 16, TM = 8;
    constexpr int TN = BN / 16;
    __shared__ float As[BK][BM];
    __shared__ float Bs[BK][BN];

    const int tid = threadIdx.x;
    const int tx = tid % 16;         // col group
    const int ty = tid / 16;         // row group
    const int rowBase = blockIdx.x * BM;

    float acc[TM][TN];
#pragma unroll
    for (int i = 0; i < TM; i++)
#pragma unroll
        for (int j = 0; j < TN; j++) acc[i][j] = 0.f;

    float asr[TN], adr[TN];
#pragma unroll
    for (int j = 0; j < TN; j++) {
        asr[j] = a_s[tx * TN + j];
        adr[j] = a_d[tx * TN + j];
    }

    for (int k0 = 0; k0 < K; k0 += BK) {
        // ---- A tile: BM x BK -> As[k][m] (transposed) ----
#pragma unroll
        for (int it = 0; it < (BM * BK) / (256 * 4); it++) {
            int idx = tid + it * 256;            // over 512 float4s
            int r = idx >> 2;                    // 0..127
            int c4 = idx & 3;                    // 0..3
            int gr = rowBase + r;
            float4 v = make_float4(0.f, 0.f, 0.f, 0.f);
            if (gr < M)
                v = *(const float4*)(A + (size_t)gr * K + k0 + c4 * 4);
            int kk = c4 * 4;
            if (TRANSFORM) {
                v.x = fmaxf(v.x * scale[k0 + kk + 0] + shift[k0 + kk + 0], 0.f);
                v.y = fmaxf(v.y * scale[k0 + kk + 1] + shift[k0 + kk + 1], 0.f);
                v.z = fmaxf(v.z * scale[k0 + kk + 2] + shift[k0 + kk + 2], 0.f);
                v.w = fmaxf(v.w * scale[k0 + kk + 3] + shift[k0 + kk + 3], 0.f);
            }
            As[kk + 0][r] = v.x;
            As[kk + 1][r] = v.y;
            As[kk + 2][r] = v.z;
            As[kk + 3][r] = v.w;
        }
        // ---- B tile: BK x BN ----
#pragma unroll
        for (int it = 0; it < (BK * BN) / (256 * 4); it++) {
            int idx = tid + it * 256;            // over BK*BN/4 float4s
            int kk = idx / (BN / 4);
            int nv = idx % (BN / 4);
            *(float4*)&Bs[kk][nv * 4] =
                *(const float4*)(B + (size_t)(k0 + kk) * BN + nv * 4);
        }
        __syncthreads();
#pragma unroll
        for (int kk = 0; kk < BK; kk++) {
            float ar[TM], br[TN];
#pragma unroll
            for (int i = 0; i < TM; i++) ar[i] = As[kk][ty * TM + i];
#pragma unroll
            for (int j = 0; j < TN; j++) br[j] = Bs[kk][tx * TN + j];
#pragma unroll
            for (int i = 0; i < TM; i++)
#pragma unroll
                for (int j = 0; j < TN; j++) acc[i][j] += ar[i] * br[j];
        }
        __syncthreads();
    }

    // ---- epilogue: store C + fused per-row s,d dot products ----
#pragma unroll
    for (int i = 0; i < TM; i++) {
        int gr = rowBase + ty * TM + i;
        float sp = 0.f, dp = 0.f;
#pragma unroll
        for (int j = 0; j < TN; j++) {
            sp += acc[i][j] * asr[j];
            dp += acc[i][j] * adr[j];
        }
        if (gr < M) {
#pragma unroll
            for (int j = 0; j < TN; j += 4)
                *(float4*)(C + (size_t)gr * BN + tx * TN + j) =
                    make_float4(acc[i][j], acc[i][j + 1], acc[i][j + 2], acc[i][j + 3]);
        }
        // reduce across the 16 threads sharing this row (contiguous lanes)
#pragma unroll
        for (int off = 8; off; off >>= 1) {
            sp += __shfl_down_sync(0xFFFFFFFFu, sp, off, 16);
            dp += __shfl_down_sync(0xFFFFFFFFu, dp, off, 16);
        }
        if (tx == 0 && gr < M) { so[gr] = sp; dout[gr] = dp; }
    }
}

// ------------------------------ CSR build --------------------------------
__global__ void hist_kernel(int E_, int n, const int* __restrict__ ei,
                            int* __restrict__ deg) {
    int e = blockIdx.x * blockDim.x + threadIdx.x;
    int tot = E_ + n;
    if (e >= tot) return;
    int dst = (e < E_) ? ei[E_ + e] : (e - E_);
    atomicAdd(&deg[dst], 1);
}

__global__ void scan1_kernel(const int* __restrict__ deg, int* __restrict__ excl,
                             int* __restrict__ bsums, int n) {
    __shared__ int sh[256];
    int tid = threadIdx.x;
    int base = blockIdx.x * 1024 + tid * 4;
    int v[4];
#pragma unroll
    for (int j = 0; j < 4; j++) v[j] = (base + j < n) ? deg[base + j] : 0;
    int tsum = v[0] + v[1] + v[2] + v[3];
    sh[tid] = tsum;
    __syncthreads();
    for (int off = 1; off < 256; off <<= 1) {
        int t = (tid >= off) ? sh[tid - off] : 0;
        __syncthreads();
        sh[tid] += t;
        __syncthreads();
    }
    int run = sh[tid] - tsum;
#pragma unroll
    for (int j = 0; j < 4; j++) {
        if (base + j < n) excl[base + j] = run;
        run += v[j];
    }
    if (tid == 255) bsums[blockIdx.x] = sh[255];
}

__global__ void scan2_kernel(int* __restrict__ bsums, int nb) {
    if (threadIdx.x == 0 && blockIdx.x == 0) {
        int acc = 0;
        for (int i = 0; i < nb; i++) { int t = bsums[i]; bsums[i] = acc; acc += t; }
    }
}

__global__ void scan3_kernel(int* __restrict__ rowptr, int* __restrict__ cursor,
                             const int* __restrict__ bsums, int n, int tot) {
    int i = blockIdx.x * blockDim.x + threadIdx.x;
    if (i < n) {
        int v = rowptr[i] + bsums[i >> 10];
        rowptr[i] = v;
        cursor[i] = v;
    }
    if (i == 0) rowptr[n] = tot;
}

__global__ void fill_kernel(int E_, int n, const int* __restrict__ ei,
                            int* __restrict__ cursor, int* __restrict__ csrc) {
    int e = blockIdx.x * blockDim.x + threadIdx.x;
    int tot = E_ + n;
    if (e >= tot) return;
    int src, dst;
    if (e < E_) { src = ei[e]; dst = ei[E_ + e]; }
    else        { src = dst = e - E_; }
    int pos = atomicAdd(&cursor[dst], 1);
    csrc[pos] = src;
}

// ---------------- fused per-dst softmax + feature aggregation ------------
template <int D>
__global__ void gat_agg_kernel(int n, const int* __restrict__ rowptr,
                               const int* __restrict__ csrc,
                               const float* __restrict__ s,
                               const float* __restrict__ dd,
                               const float* __restrict__ Hm,
                               float* __restrict__ out) {
    constexpr int V = D / 32;
    int w = (blockIdx.x * blockDim.x + threadIdx.x) >> 5;
    int lane = threadIdx.x & 31;
    if (w >= n) return;
    int start = rowptr[w];
    int end = rowptr[w + 1];
    float dv = dd[w];

    float m = -1e30f, den = 0.f;
    for (int i = start + lane; i < end; i += 32) {
        float lg = s[csrc[i]] + dv;
        lg = lg > 0.f ? lg : 0.2f * lg;
        if (lg > m) { den = den * __expf(m - lg) + 1.f; m = lg; }
        else        { den += __expf(lg - m); }
    }
#pragma unroll
    for (int o = 16; o; o >>= 1) {
        float mo = __shfl_xor_sync(0xFFFFFFFFu, m, o);
        float do_ = __shfl_xor_sync(0xFFFFFFFFu, den, o);
        float mn = fmaxf(m, mo);
        den = den * __expf(m - mn) + do_ * __expf(mo - mn);
        m = mn;
    }
    float inv = 1.f / den;

    float acc[V];
#pragma unroll
    for (int j = 0; j < V; j++) acc[j] = 0.f;

    for (int base = start; base < end; base += 32) {
        int i = base + lane;
        int srcv = 0;
        float wv = 0.f;
        if (i < end) {
            srcv = csrc[i];
            float lg = s[srcv] + dv;
            lg = lg > 0.f ? lg : 0.2f * lg;
            wv = __expf(lg - m) * inv;
        }
        int cnt = min(32, end - base);
        for (int k = 0; k < cnt; k++) {
            float c = __shfl_sync(0xFFFFFFFFu, wv, k);
            int sc = __shfl_sync(0xFFFFFFFFu, srcv, k);
            if (V == 4) {
                float4 v = ((const float4*)(Hm + (size_t)sc * D))[lane];
                acc[0] += c * v.x; acc[1] += c * v.y;
                acc[2] += c * v.z; acc[3] += c * v.w;
            } else {
                float2 v = ((const float2*)(Hm + (size_t)sc * D))[lane];
                acc[0] += c * v.x; acc[1] += c * v.y;
            }
        }
    }
    if (V == 4) {
        ((float4*)(out + (size_t)w * D))[lane] =
            make_float4(acc[0], acc[1], acc[2], acc[3]);
    } else {
        ((float2*)(out + (size_t)w * D))[lane] = make_float2(acc[0], acc[1]);
    }
}

// ---------------------------- BatchNorm ----------------------------------
template <int D>
__global__ void bn_stats_kernel(int n, const float* __restrict__ x,
                                float* __restrict__ stats) {
    int c = threadIdx.x;          // blockDim.x == D
    int r0 = blockIdx.x * 64;
    int r1 = min(r0 + 64, n);
    float s = 0.f, q = 0.f;
    for (int r = r0; r < r1; r++) {
        float v = x[(size_t)r * D + c];
        s += v;
        q += v * v;
    }
    atomicAdd(&stats[c], s);
    atomicAdd(&stats[128 + c], q);
}

template <int D>
__global__ void bn_finalize_kernel(int n, const float* __restrict__ stats,
                                   const float* __restrict__ g,
                                   const float* __restrict__ b,
                                   float* __restrict__ scale,
                                   float* __restrict__ shift) {
    int c = threadIdx.x;
    if (c >= D) return;
    float invn = 1.f / (float)n;
    float mu = stats[c] * invn;
    float var = stats[128 + c] * invn - mu * mu;
    float sc = g[c] * rsqrtf(var + EPS);
    scale[c] = sc;
    shift[c] = b[c] - mu * sc;
}

template <int D>
__global__ void bn_apply_kernel(int n, float* __restrict__ x,
                                const float* __restrict__ scale,
                                const float* __restrict__ shift) {
    int i = blockIdx.x * blockDim.x + threadIdx.x;
    if (i >= n * D) return;
    int c = i % D;
    x[i] = fmaxf(x[i] * scale[c] + shift[c], 0.f);
}

// ------------------------------ launcher ---------------------------------
extern "C" void kernel_launch(void* const* d_in, const int* in_sizes, int n_in,
                              void* d_out, int out_size) {
    const float* x   = (const float*)d_in[0];
    const int*   ei  = (const int*)d_in[1];
    const float* W0  = (const float*)d_in[2];
    const float* as0 = (const float*)d_in[3];
    const float* ad0 = (const float*)d_in[4];
    const float* gg0 = (const float*)d_in[5];
    const float* bb0 = (const float*)d_in[6];
    const float* W1  = (const float*)d_in[7];
    const float* as1 = (const float*)d_in[8];
    const float* ad1 = (const float*)d_in[9];
    const float* gg1 = (const float*)d_in[10];
    const float* bb1 = (const float*)d_in[11];

    const int F = 128, Hd = 128, C = 64;
    const int n  = in_sizes[0] / F;
    const int E_ = in_sizes[1] / 2;
    const int tot = E_ + n;
    float* out = (float*)d_out;

    float *hbuf, *abuf, *sbuf, *dbuf, *statb, *scaleb, *shiftb;
    int *degb, *rowp, *curs, *csrc, *bsums;
    cudaGetSymbolAddress((void**)&hbuf, g_h);
    cudaGetSymbolAddress((void**)&abuf, g_agg);
    cudaGetSymbolAddress((void**)&sbuf, g_s);
    cudaGetSymbolAddress((void**)&dbuf, g_d);
    cudaGetSymbolAddress((void**)&statb, g_stats);
    cudaGetSymbolAddress((void**)&scaleb, g_scale);
    cudaGetSymbolAddress((void**)&shiftb, g_shift);
    cudaGetSymbolAddress((void**)&degb, g_deg);
    cudaGetSymbolAddress((void**)&rowp, g_rowptr);
    cudaGetSymbolAddress((void**)&curs, g_cursor);
    cudaGetSymbolAddress((void**)&csrc, g_csrc);
    cudaGetSymbolAddress((void**)&bsums, g_bsums);

    // ======================= CSR build (shared by both layers) ============
    cudaMemsetAsync(degb, 0, (size_t)n * sizeof(int));
    hist_kernel<<<(tot + 255) / 256, 256>>>(E_, n, ei, degb);
    int nb = (n + 1023) / 1024;
    scan1_kernel<<<nb, 256>>>(degb, rowp, bsums, n);
    scan2_kernel<<<1, 32>>>(bsums, nb);
    scan3_kernel<<<(n + 255) / 256, 256>>>(rowp, curs, bsums, n, tot);
    fill_kernel<<<(tot + 255) / 256, 256>>>(E_, n, ei, curs, csrc);

    // ============================ Layer 0 =================================
    sgemm_fused_kernel<128, false><<<(n + 127) / 128, 256>>>(
        n, F, x, W0, hbuf, as0, ad0, sbuf, dbuf, nullptr, nullptr);
    gat_agg_kernel<128><<<(n * 32 + 255) / 256, 256>>>(n, rowp, csrc, sbuf, dbuf, hbuf, abuf);

    cudaMemsetAsync(statb, 0, 256 * sizeof(float));
    bn_stats_kernel<128><<<(n + 63) / 64, 128>>>(n, abuf, statb);
    bn_finalize_kernel<128><<<1, 128>>>(n, statb, gg0, bb0, scaleb, shiftb);

    // ============================ Layer 1 =================================
    // BN+ReLU of layer 0 fused into the A-tile load.
    sgemm_fused_kernel<64, true><<<(n + 127) / 128, 256>>>(
        n, Hd, abuf, W1, hbuf, as1, ad1, sbuf, dbuf, scaleb, shiftb);
    gat_agg_kernel<64><<<(n * 32 + 255) / 256, 256>>>(n, rowp, csrc, sbuf, dbuf, hbuf, out);

    cudaMemsetAsync(statb, 0, 256 * sizeof(float));
    bn_stats_kernel<64><<<(n + 63) / 64, 64>>>(n, out, statb);
    bn_finalize_kernel<64><<<1, 64>>>(n, statb, gg1, bb1, scaleb, shiftb);
    bn_apply_kernel<64><<<((long long)n * C + 255) / 256, 256>>>(n, out, scaleb, shiftb);
}

// round 5
// speedup vs baseline: 2.2079x; 1.0544x over previous
#include <cuda_runtime.h>
#include <cuda_bf16.h>
#include <cstdint>

#define NMAX 100000
#define EMAX 1700000
#define EPS 1e-5f

// -------- scratch (static device globals; no allocation allowed) --------
__device__ float g_h[(size_t)NMAX * 128];
__device__ float g_agg[(size_t)NMAX * 128];
__device__ float g_s[NMAX];
__device__ float g_d[NMAX];
__device__ int   g_deg[NMAX];
__device__ int   g_rowptr[NMAX + 1];
__device__ int   g_cursor[NMAX];
__device__ int   g_csrc[EMAX];
__device__ int   g_bsums[256];
__device__ float g_stats[256];
__device__ float g_scale[128];
__device__ float g_shift[128];

// ---------------------- packed f32x2 helpers ------------------------------
__device__ __forceinline__ void fma2(uint64_t& d, uint64_t a, uint64_t b) {
    asm("fma.rn.f32x2 %0, %1, %2, %3;" : "=l"(d) : "l"(a), "l"(b), "l"(d));
}
__device__ __forceinline__ uint64_t dup2(float x) {
    uint64_t r;
    asm("mov.b64 %0, {%1, %1};" : "=l"(r) : "f"(x));
    return r;
}
__device__ __forceinline__ float2 unpack2(uint64_t v) {
    float2 f;
    asm("mov.b64 {%0, %1}, %2;" : "=f"(f.x), "=f"(f.y) : "l"(v));
    return f;
}

// ------------------------------- SGEMM ----------------------------------
// C[M,N] = A'[M,K] @ B[K,N]; BN == N (single block column). Optionally A is
// transformed on load: a = max(0, a*scale[k] + shift[k]) (fused BN+ReLU of the
// previous layer). Fused epilogue computes per-row s = C·a_s, d = C·a_d.
// BM=128, BK=16, 256 threads, TM=8, TN=BN/16. Inner product uses packed
// fma.rn.f32x2 (FFMA2) for 2x FMA issue density.
template <int BN, bool TRANSFORM>
__global__ __launch_bounds__(256) void sgemm_fused_kernel(
    int M, int K,
    const float* __restrict__ A,
    const float* __restrict__ B,
    float* __restrict__ C,
    const float* __restrict__ a_s,
    const float* __restrict__ a_d,
    float* __restrict__ so, float* __restrict__ dout,
    const float* __restrict__ scale,
    const float* __restrict__ shift) {
    constexpr int BM = 128, BK = 16, TM = 8;
    constexpr int TN = BN / 16;
    constexpr int TP = TN / 2;
    __shared__ float As[BK][BM];
    __shared__ float Bs[BK][BN];

    const int tid = threadIdx.x;
    const int tx = tid % 16;
    const int ty = tid / 16;
    const int rowBase = blockIdx.x * BM;

    uint64_t acc2[TM][TP];
#pragma unroll
    for (int i = 0; i < TM; i++)
#pragma unroll
        for (int j = 0; j < TP; j++) acc2[i][j] = 0ull;

    float asr[TN], adr[TN];
#pragma unroll
    for (int j = 0; j < TN; j++) {
        asr[j] = a_s[tx * TN + j];
        adr[j] = a_d[tx * TN + j];
    }

    for (int k0 = 0; k0 < K; k0 += BK) {
        // ---- A tile: BM x BK -> As[k][m] (transposed) ----
#pragma unroll
        for (int it = 0; it < (BM * BK) / (256 * 4); it++) {
            int idx = tid + it * 256;
            int r = idx >> 2;
            int c4 = idx & 3;
            int gr = rowBase + r;
            float4 v = make_float4(0.f, 0.f, 0.f, 0.f);
            if (gr < M)
                v = *(const float4*)(A + (size_t)gr * K + k0 + c4 * 4);
            int kk = c4 * 4;
            if (TRANSFORM) {
                v.x = fmaxf(v.x * scale[k0 + kk + 0] + shift[k0 + kk + 0], 0.f);
                v.y = fmaxf(v.y * scale[k0 + kk + 1] + shift[k0 + kk + 1], 0.f);
                v.z = fmaxf(v.z * scale[k0 + kk + 2] + shift[k0 + kk + 2], 0.f);
                v.w = fmaxf(v.w * scale[k0 + kk + 3] + shift[k0 + kk + 3], 0.f);
            }
            As[kk + 0][r] = v.x;
            As[kk + 1][r] = v.y;
            As[kk + 2][r] = v.z;
            As[kk + 3][r] = v.w;
        }
        // ---- B tile: BK x BN ----
#pragma unroll
        for (int it = 0; it < (BK * BN) / (256 * 4); it++) {
            int idx = tid + it * 256;
            int kk = idx / (BN / 4);
            int nv = idx % (BN / 4);
            *(float4*)&Bs[kk][nv * 4] =
                *(const float4*)(B + (size_t)(k0 + kk) * BN + nv * 4);
        }
        __syncthreads();
#pragma unroll
        for (int kk = 0; kk < BK; kk++) {
            float4 a0 = *(const float4*)&As[kk][ty * TM];
            float4 a1 = *(const float4*)&As[kk][ty * TM + 4];
            uint64_t ad[TM];
            ad[0] = dup2(a0.x); ad[1] = dup2(a0.y);
            ad[2] = dup2(a0.z); ad[3] = dup2(a0.w);
            ad[4] = dup2(a1.x); ad[5] = dup2(a1.y);
            ad[6] = dup2(a1.z); ad[7] = dup2(a1.w);
            uint64_t b2[TP];
            const uint64_t* bp = (const uint64_t*)&Bs[kk][tx * TN];
#pragma unroll
            for (int j = 0; j < TP; j++) b2[j] = bp[j];
#pragma unroll
            for (int i = 0; i < TM; i++)
#pragma unroll
                for (int j = 0; j < TP; j++) fma2(acc2[i][j], ad[i], b2[j]);
        }
        __syncthreads();
    }

    // ---- epilogue: store C + fused per-row s,d dot products ----
#pragma unroll
    for (int i = 0; i < TM; i++) {
        int gr = rowBase + ty * TM + i;
        float vals[TN];
#pragma unroll
        for (int j = 0; j < TP; j++) {
            float2 f = unpack2(acc2[i][j]);
            vals[2 * j] = f.x;
            vals[2 * j + 1] = f.y;
        }
        float sp = 0.f, dp = 0.f;
#pragma unroll
        for (int j = 0; j < TN; j++) {
            sp += vals[j] * asr[j];
            dp += vals[j] * adr[j];
        }
        if (gr < M) {
#pragma unroll
            for (int j = 0; j < TN; j += 4)
                *(float4*)(C + (size_t)gr * BN + tx * TN + j) =
                    make_float4(vals[j], vals[j + 1], vals[j + 2], vals[j + 3]);
        }
#pragma unroll
        for (int off = 8; off; off >>= 1) {
            sp += __shfl_down_sync(0xFFFFFFFFu, sp, off, 16);
            dp += __shfl_down_sync(0xFFFFFFFFu, dp, off, 16);
        }
        if (tx == 0 && gr < M) { so[gr] = sp; dout[gr] = dp; }
    }
}

// ------------------------------ CSR build --------------------------------
__global__ void hist_kernel(int E_, int n, const int* __restrict__ ei,
                            int* __restrict__ deg) {
    int e = blockIdx.x * blockDim.x + threadIdx.x;
    int tot = E_ + n;
    if (e >= tot) return;
    int dst = (e < E_) ? ei[E_ + e] : (e - E_);
    atomicAdd(&deg[dst], 1);
}

__global__ void scan1_kernel(const int* __restrict__ deg, int* __restrict__ excl,
                             int* __restrict__ bsums, int n) {
    __shared__ int sh[256];
    int tid = threadIdx.x;
    int base = blockIdx.x * 1024 + tid * 4;
    int v[4];
#pragma unroll
    for (int j = 0; j < 4; j++) v[j] = (base + j < n) ? deg[base + j] : 0;
    int tsum = v[0] + v[1] + v[2] + v[3];
    sh[tid] = tsum;
    __syncthreads();
    for (int off = 1; off < 256; off <<= 1) {
        int t = (tid >= off) ? sh[tid - off] : 0;
        __syncthreads();
        sh[tid] += t;
        __syncthreads();
    }
    int run = sh[tid] - tsum;
#pragma unroll
    for (int j = 0; j < 4; j++) {
        if (base + j < n) excl[base + j] = run;
        run += v[j];
    }
    if (tid == 255) bsums[blockIdx.x] = sh[255];
}

__global__ void scan2_kernel(int* __restrict__ bsums, int nb) {
    if (threadIdx.x == 0 && blockIdx.x == 0) {
        int acc = 0;
        for (int i = 0; i < nb; i++) { int t = bsums[i]; bsums[i] = acc; acc += t; }
    }
}

__global__ void scan3_kernel(int* __restrict__ rowptr, int* __restrict__ cursor,
                             const int* __restrict__ bsums, int n, int tot) {
    int i = blockIdx.x * blockDim.x + threadIdx.x;
    if (i < n) {
        int v = rowptr[i] + bsums[i >> 10];
        rowptr[i] = v;
        cursor[i] = v;
    }
    if (i == 0) rowptr[n] = tot;
}

__global__ void fill_kernel(int E_, int n, const int* __restrict__ ei,
                            int* __restrict__ cursor, int* __restrict__ csrc) {
    int e = blockIdx.x * blockDim.x + threadIdx.x;
    int tot = E_ + n;
    if (e >= tot) return;
    int src, dst;
    if (e < E_) { src = ei[e]; dst = ei[E_ + e]; }
    else        { src = dst = e - E_; }
    int pos = atomicAdd(&cursor[dst], 1);
    csrc[pos] = src;
}

// ---------------- fused per-dst softmax + feature aggregation ------------
template <int D>
__global__ void gat_agg_kernel(int n, const int* __restrict__ rowptr,
                               const int* __restrict__ csrc,
                               const float* __restrict__ s,
                               const float* __restrict__ dd,
                               const float* __restrict__ Hm,
                               float* __restrict__ out) {
    constexpr int V = D / 32;
    int w = (blockIdx.x * blockDim.x + threadIdx.x) >> 5;
    int lane = threadIdx.x & 31;
    if (w >= n) return;
    int start = rowptr[w];
    int end = rowptr[w + 1];
    float dv = dd[w];

    float m = -1e30f, den = 0.f;
    for (int i = start + lane; i < end; i += 32) {
        float lg = s[csrc[i]] + dv;
        lg = lg > 0.f ? lg : 0.2f * lg;
        if (lg > m) { den = den * __expf(m - lg) + 1.f; m = lg; }
        else        { den += __expf(lg - m); }
    }
#pragma unroll
    for (int o = 16; o; o >>= 1) {
        float mo = __shfl_xor_sync(0xFFFFFFFFu, m, o);
        float do_ = __shfl_xor_sync(0xFFFFFFFFu, den, o);
        float mn = fmaxf(m, mo);
        den = den * __expf(m - mn) + do_ * __expf(mo - mn);
        m = mn;
    }
    float inv = 1.f / den;

    float acc[V];
#pragma unroll
    for (int j = 0; j < V; j++) acc[j] = 0.f;

    for (int base = start; base < end; base += 32) {
        int i = base + lane;
        int srcv = 0;
        float wv = 0.f;
        if (i < end) {
            srcv = csrc[i];
            float lg = s[srcv] + dv;
            lg = lg > 0.f ? lg : 0.2f * lg;
            wv = __expf(lg - m) * inv;
        }
        int cnt = min(32, end - base);
        for (int k = 0; k < cnt; k++) {
            float c = __shfl_sync(0xFFFFFFFFu, wv, k);
            int sc = __shfl_sync(0xFFFFFFFFu, srcv, k);
            if (V == 4) {
                float4 v = ((const float4*)(Hm + (size_t)sc * D))[lane];
                acc[0] += c * v.x; acc[1] += c * v.y;
                acc[2] += c * v.z; acc[3] += c * v.w;
            } else {
                float2 v = ((const float2*)(Hm + (size_t)sc * D))[lane];
                acc[0] += c * v.x; acc[1] += c * v.y;
            }
        }
    }
    if (V == 4) {
        ((float4*)(out + (size_t)w * D))[lane] =
            make_float4(acc[0], acc[1], acc[2], acc[3]);
    } else {
        ((float2*)(out + (size_t)w * D))[lane] = make_float2(acc[0], acc[1]);
    }
}

// ---------------------------- BatchNorm ----------------------------------
template <int D>
__global__ void bn_stats_kernel(int n, const float* __restrict__ x,
                                float* __restrict__ stats) {
    int c = threadIdx.x;          // blockDim.x == D
    int r0 = blockIdx.x * 64;
    int r1 = min(r0 + 64, n);
    float s = 0.f, q = 0.f;
    for (int r = r0; r < r1; r++) {
        float v = x[(size_t)r * D + c];
        s += v;
        q += v * v;
    }
    atomicAdd(&stats[c], s);
    atomicAdd(&stats[128 + c], q);
}

template <int D>
__global__ void bn_finalize_kernel(int n, const float* __restrict__ stats,
                                   const float* __restrict__ g,
                                   const float* __restrict__ b,
                                   float* __restrict__ scale,
                                   float* __restrict__ shift) {
    int c = threadIdx.x;
    if (c >= D) return;
    float invn = 1.f / (float)n;
    float mu = stats[c] * invn;
    float var = stats[128 + c] * invn - mu * mu;
    float sc = g[c] * rsqrtf(var + EPS);
    scale[c] = sc;
    shift[c] = b[c] - mu * sc;
}

template <int D>
__global__ void bn_apply_kernel(int n, float* __restrict__ x,
                                const float* __restrict__ scale,
                                const float* __restrict__ shift) {
    int i = blockIdx.x * blockDim.x + threadIdx.x;
    if (i >= n * D) return;
    int c = i % D;
    x[i] = fmaxf(x[i] * scale[c] + shift[c], 0.f);
}

// ------------------------------ launcher ---------------------------------
extern "C" void kernel_launch(void* const* d_in, const int* in_sizes, int n_in,
                              void* d_out, int out_size) {
    const float* x   = (const float*)d_in[0];
    const int*   ei  = (const int*)d_in[1];
    const float* W0  = (const float*)d_in[2];
    const float* as0 = (const float*)d_in[3];
    const float* ad0 = (const float*)d_in[4];
    const float* gg0 = (const float*)d_in[5];
    const float* bb0 = (const float*)d_in[6];
    const float* W1  = (const float*)d_in[7];
    const float* as1 = (const float*)d_in[8];
    const float* ad1 = (const float*)d_in[9];
    const float* gg1 = (const float*)d_in[10];
    const float* bb1 = (const float*)d_in[11];

    const int F = 128, Hd = 128, C = 64;
    const int n  = in_sizes[0] / F;
    const int E_ = in_sizes[1] / 2;
    const int tot = E_ + n;
    float* out = (float*)d_out;

    float *hbuf, *abuf, *sbuf, *dbuf, *statb, *scaleb, *shiftb;
    int *degb, *rowp, *curs, *csrc, *bsums;
    cudaGetSymbolAddress((void**)&hbuf, g_h);
    cudaGetSymbolAddress((void**)&abuf, g_agg);
    cudaGetSymbolAddress((void**)&sbuf, g_s);
    cudaGetSymbolAddress((void**)&dbuf, g_d);
    cudaGetSymbolAddress((void**)&statb, g_stats);
    cudaGetSymbolAddress((void**)&scaleb, g_scale);
    cudaGetSymbolAddress((void**)&shiftb, g_shift);
    cudaGetSymbolAddress((void**)&degb, g_deg);
    cudaGetSymbolAddress((void**)&rowp, g_rowptr);
    cudaGetSymbolAddress((void**)&curs, g_cursor);
    cudaGetSymbolAddress((void**)&csrc, g_csrc);
    cudaGetSymbolAddress((void**)&bsums, g_bsums);

    // ======================= CSR build (shared by both layers) ============
    cudaMemsetAsync(degb, 0, (size_t)n * sizeof(int));
    hist_kernel<<<(tot + 255) / 256, 256>>>(E_, n, ei, degb);
    int nb = (n + 1023) / 1024;
    scan1_kernel<<<nb, 256>>>(degb, rowp, bsums, n);
    scan2_kernel<<<1, 32>>>(bsums, nb);
    scan3_kernel<<<(n + 255) / 256, 256>>>(rowp, curs, bsums, n, tot);
    fill_kernel<<<(tot + 255) / 256, 256>>>(E_, n, ei, curs, csrc);

    // ============================ Layer 0 =================================
    sgemm_fused_kernel<128, false><<<(n + 127) / 128, 256>>>(
        n, F, x, W0, hbuf, as0, ad0, sbuf, dbuf, nullptr, nullptr);
    gat_agg_kernel<128><<<(n * 32 + 255) / 256, 256>>>(n, rowp, csrc, sbuf, dbuf, hbuf, abuf);

    cudaMemsetAsync(statb, 0, 256 * sizeof(float));
    bn_stats_kernel<128><<<(n + 63) / 64, 128>>>(n, abuf, statb);
    bn_finalize_kernel<128><<<1, 128>>>(n, statb, gg0, bb0, scaleb, shiftb);

    // ============================ Layer 1 =================================
    sgemm_fused_kernel<64, true><<<(n + 127) / 128, 256>>>(
        n, Hd, abuf, W1, hbuf, as1, ad1, sbuf, dbuf, scaleb, shiftb);
    gat_agg_kernel<64><<<(n * 32 + 255) / 256, 256>>>(n, rowp, csrc, sbuf, dbuf, hbuf, out);

    cudaMemsetAsync(statb, 0, 256 * sizeof(float));
    bn_stats_kernel<64><<<(n + 63) / 64, 64>>>(n, out, statb);
    bn_finalize_kernel<64><<<1, 64>>>(n, statb, gg1, bb1, scaleb, shiftb);
    bn_apply_kernel<64><<<((long long)n * C + 255) / 256, 256>>>(n, out, scaleb, shiftb);
}

// round 7
// speedup vs baseline: 2.5427x; 1.1517x over previous
#include <cuda_runtime.h>
#include <cuda_fp16.h>
#include <cstdint>

#define NMAX 100000
#define EMAX 1700000
#define EPS 1e-5f

// -------- scratch (static device globals; no allocation allowed) --------
__device__ __half g_h[(size_t)NMAX * 128];   // GEMM output h in fp16
__device__ float g_agg[(size_t)NMAX * 128];  // layer-0 aggregation (pre-BN)
__device__ float g_s[NMAX];
__device__ float g_d[NMAX];
__device__ int   g_deg[NMAX];
__device__ int   g_rowptr[NMAX + 1];
__device__ int   g_cursor[NMAX];
__device__ int   g_csrc[EMAX];
__device__ int   g_bsums[256];
__device__ float g_stats[256];
__device__ float g_scale[128];
__device__ float g_shift[128];

// ---------------------- packed f32x2 helpers ------------------------------
__device__ __forceinline__ void fma2(uint64_t& d, uint64_t a, uint64_t b) {
    asm("fma.rn.f32x2 %0, %1, %2, %3;" : "=l"(d) : "l"(a), "l"(b), "l"(d));
}
__device__ __forceinline__ uint64_t dup2(float x) {
    uint64_t r;
    asm("mov.b64 %0, {%1, %1};" : "=l"(r) : "f"(x));
    return r;
}
__device__ __forceinline__ float2 unpack2(uint64_t v) {
    float2 f;
    asm("mov.b64 {%0, %1}, %2;" : "=f"(f.x), "=f"(f.y) : "l"(v));
    return f;
}

// ------------------------------- SGEMM ----------------------------------
// C[M,N] (fp16) = A[M,K] @ B[K,N]; BN == N (one block column). Optional fused
// BN+ReLU transform on A load. Fused per-row s = C·a_s, d = C·a_d (fp32).
// BM=128, BK=16, 256 threads, TM=8, TN=BN/16, packed FFMA2 inner product,
// register-prefetch double buffering of global loads.
template <int BN, bool TRANSFORM>
__global__ __launch_bounds__(256) void sgemm_fused_kernel(
    int M, int K,
    const float* __restrict__ A,
    const float* __restrict__ B,
    __half* __restrict__ C,
    const float* __restrict__ a_s,
    const float* __restrict__ a_d,
    float* __restrict__ so, float* __restrict__ dout,
    const float* __restrict__ scale,
    const float* __restrict__ shift) {
    constexpr int BM = 128, BK = 16, TM = 8;
    constexpr int TN = BN / 16;
    constexpr int TP = TN / 2;
    constexpr int NA = 2;                 // A float4 regs per thread
    constexpr int NB = (BK * BN) / 1024;  // B float4 regs per thread (2 or 1)
    __shared__ float As[BK][BM];
    __shared__ float Bs[BK][BN];

    const int tid = threadIdx.x;
    const int tx = tid % 16;
    const int ty = tid / 16;
    const int rowBase = blockIdx.x * BM;

    uint64_t acc2[TM][TP];
#pragma unroll
    for (int i = 0; i < TM; i++)
#pragma unroll
        for (int j = 0; j < TP; j++) acc2[i][j] = 0ull;

    float asr[TN], adr[TN];
#pragma unroll
    for (int j = 0; j < TN; j++) {
        asr[j] = a_s[tx * TN + j];
        adr[j] = a_d[tx * TN + j];
    }

    float4 ra[NA], rb[NB];
    // prefetch tile 0
#pragma unroll
    for (int it = 0; it < NA; it++) {
        int idx = tid + it * 256;
        int r = idx >> 2, c4 = idx & 3;
        int gr = rowBase + r;
        ra[it] = (gr < M) ? *(const float4*)(A + (size_t)gr * K + c4 * 4)
                          : make_float4(0.f, 0.f, 0.f, 0.f);
    }
#pragma unroll
    for (int it = 0; it < NB; it++) {
        int idx = tid + it * 256;
        int kk = idx / (BN / 4), nv = idx % (BN / 4);
        rb[it] = *(const float4*)(B + (size_t)kk * BN + nv * 4);
    }

    for (int k0 = 0; k0 < K; k0 += BK) {
        // ---- store prefetched tile to smem (A transposed, with transform) ----
#pragma unroll
        for (int it = 0; it < NA; it++) {
            int idx = tid + it * 256;
            int r = idx >> 2, c4 = idx & 3;
            float4 v = ra[it];
            int kk = c4 * 4;
            if (TRANSFORM) {
                v.x = fmaxf(v.x * scale[k0 + kk + 0] + shift[k0 + kk + 0], 0.f);
                v.y = fmaxf(v.y * scale[k0 + kk + 1] + shift[k0 + kk + 1], 0.f);
                v.z = fmaxf(v.z * scale[k0 + kk + 2] + shift[k0 + kk + 2], 0.f);
                v.w = fmaxf(v.w * scale[k0 + kk + 3] + shift[k0 + kk + 3], 0.f);
            }
            As[kk + 0][r] = v.x;
            As[kk + 1][r] = v.y;
            As[kk + 2][r] = v.z;
            As[kk + 3][r] = v.w;
        }
#pragma unroll
        for (int it = 0; it < NB; it++) {
            int idx = tid + it * 256;
            int kk = idx / (BN / 4), nv = idx % (BN / 4);
            *(float4*)&Bs[kk][nv * 4] = rb[it];
        }
        __syncthreads();
        // ---- prefetch next tile into regs ----
        if (k0 + BK < K) {
            int kn = k0 + BK;
#pragma unroll
            for (int it = 0; it < NA; it++) {
                int idx = tid + it * 256;
                int r = idx >> 2, c4 = idx & 3;
                int gr = rowBase + r;
                ra[it] = (gr < M) ? *(const float4*)(A + (size_t)gr * K + kn + c4 * 4)
                                  : make_float4(0.f, 0.f, 0.f, 0.f);
            }
#pragma unroll
            for (int it = 0; it < NB; it++) {
                int idx = tid + it * 256;
                int kk = idx / (BN / 4), nv = idx % (BN / 4);
                rb[it] = *(const float4*)(B + (size_t)(kn + kk) * BN + nv * 4);
            }
        }
        // ---- compute ----
#pragma unroll
        for (int kk = 0; kk < BK; kk++) {
            float4 a0 = *(const float4*)&As[kk][ty * TM];
            float4 a1 = *(const float4*)&As[kk][ty * TM + 4];
            uint64_t ad[TM];
            ad[0] = dup2(a0.x); ad[1] = dup2(a0.y);
            ad[2] = dup2(a0.z); ad[3] = dup2(a0.w);
            ad[4] = dup2(a1.x); ad[5] = dup2(a1.y);
            ad[6] = dup2(a1.z); ad[7] = dup2(a1.w);
            uint64_t b2[TP];
            const uint64_t* bp = (const uint64_t*)&Bs[kk][tx * TN];
#pragma unroll
            for (int j = 0; j < TP; j++) b2[j] = bp[j];
#pragma unroll
            for (int i = 0; i < TM; i++)
#pragma unroll
                for (int j = 0; j < TP; j++) fma2(acc2[i][j], ad[i], b2[j]);
        }
        __syncthreads();
    }

    // ---- epilogue: store fp16 C + fused per-row s,d dot products ----
#pragma unroll
    for (int i = 0; i < TM; i++) {
        int gr = rowBase + ty * TM + i;
        float vals[TN];
#pragma unroll
        for (int j = 0; j < TP; j++) {
            float2 f = unpack2(acc2[i][j]);
            vals[2 * j] = f.x;
            vals[2 * j + 1] = f.y;
        }
        float sp = 0.f, dp = 0.f;
#pragma unroll
        for (int j = 0; j < TN; j++) {
            sp += vals[j] * asr[j];
            dp += vals[j] * adr[j];
        }
        if (gr < M) {
            __half2 hv[TP];
#pragma unroll
            for (int j = 0; j < TP; j++)
                hv[j] = __floats2half2_rn(vals[2 * j], vals[2 * j + 1]);
            // TN halfs = TN*2 bytes: TP==4 -> 16B (uint4), TP==2 -> 8B (uint2)
            if (TP == 4)
                *(uint4*)(C + (size_t)gr * BN + tx * TN) = *(uint4*)hv;
            else
                *(uint2*)(C + (size_t)gr * BN + tx * TN) = *(uint2*)hv;
        }
#pragma unroll
        for (int off = 8; off; off >>= 1) {
            sp += __shfl_down_sync(0xFFFFFFFFu, sp, off, 16);
            dp += __shfl_down_sync(0xFFFFFFFFu, dp, off, 16);
        }
        if (tx == 0 && gr < M) { so[gr] = sp; dout[gr] = dp; }
    }
}

// ------------------------------ CSR build --------------------------------
__global__ void hist_kernel(int E_, int n, const int* __restrict__ ei,
                            int* __restrict__ deg) {
    int e = blockIdx.x * blockDim.x + threadIdx.x;
    int tot = E_ + n;
    if (e >= tot) return;
    int dst = (e < E_) ? ei[E_ + e] : (e - E_);
    atomicAdd(&deg[dst], 1);
}

__global__ void scan1_kernel(const int* __restrict__ deg, int* __restrict__ excl,
                             int* __restrict__ bsums, int n) {
    __shared__ int sh[256];
    int tid = threadIdx.x;
    int base = blockIdx.x * 1024 + tid * 4;
    int v[4];
#pragma unroll
    for (int j = 0; j < 4; j++) v[j] = (base + j < n) ? deg[base + j] : 0;
    int tsum = v[0] + v[1] + v[2] + v[3];
    sh[tid] = tsum;
    __syncthreads();
    for (int off = 1; off < 256; off <<= 1) {
        int t = (tid >= off) ? sh[tid - off] : 0;
        __syncthreads();
        sh[tid] += t;
        __syncthreads();
    }
    int run = sh[tid] - tsum;
#pragma unroll
    for (int j = 0; j < 4; j++) {
        if (base + j < n) excl[base + j] = run;
        run += v[j];
    }
    if (tid == 255) bsums[blockIdx.x] = sh[255];
}

__global__ void scan2_kernel(int* __restrict__ bsums, int nb) {
    if (threadIdx.x == 0 && blockIdx.x == 0) {
        int acc = 0;
        for (int i = 0; i < nb; i++) { int t = bsums[i]; bsums[i] = acc; acc += t; }
    }
}

__global__ void scan3_kernel(int* __restrict__ rowptr, int* __restrict__ cursor,
                             const int* __restrict__ bsums, int n, int tot) {
    int i = blockIdx.x * blockDim.x + threadIdx.x;
    if (i < n) {
        int v = rowptr[i] + bsums[i >> 10];
        rowptr[i] = v;
        cursor[i] = v;
    }
    if (i == 0) rowptr[n] = tot;
}

__global__ void fill_kernel(int E_, int n, const int* __restrict__ ei,
                            int* __restrict__ cursor, int* __restrict__ csrc) {
    int e = blockIdx.x * blockDim.x + threadIdx.x;
    int tot = E_ + n;
    if (e >= tot) return;
    int src, dst;
    if (e < E_) { src = ei[e]; dst = ei[E_ + e]; }
    else        { src = dst = e - E_; }
    int pos = atomicAdd(&cursor[dst], 1);
    csrc[pos] = src;
}

// ---------- single-pass per-dst softmax + feature aggregation ------------
// One warp per dst. Softmax is shift-invariant and logits are bounded, so no
// max pass: acc = sum(exp(lg) * h_src), den = sum(exp(lg)), out = acc / den.
template <int D>
__global__ void gat_agg_kernel(int n, const int* __restrict__ rowptr,
                               const int* __restrict__ csrc,
                               const float* __restrict__ s,
                               const float* __restrict__ dd,
                               const __half* __restrict__ Hm,
                               float* __restrict__ out) {
    constexpr int V = D / 32;   // fp32 acc per lane (4 for D=128, 2 for D=64)
    int w = (blockIdx.x * blockDim.x + threadIdx.x) >> 5;
    int lane = threadIdx.x & 31;
    if (w >= n) return;
    int start = rowptr[w];
    int end = rowptr[w + 1];
    float dv = dd[w];

    float den = 0.f;
    float acc[V];
#pragma unroll
    for (int j = 0; j < V; j++) acc[j] = 0.f;

    for (int base = start; base < end; base += 32) {
        int i = base + lane;
        int srcv = 0;
        float wv = 0.f;
        if (i < end) {
            srcv = csrc[i];
            float lg = s[srcv] + dv;
            lg = lg > 0.f ? lg : 0.2f * lg;
            wv = __expf(lg);
        }
        den += wv;
        int cnt = min(32, end - base);
        for (int k = 0; k < cnt; k++) {
            float c = __shfl_sync(0xFFFFFFFFu, wv, k);
            int sc = __shfl_sync(0xFFFFFFFFu, srcv, k);
            if (V == 4) {
                uint2 u = ((const uint2*)(Hm + (size_t)sc * D))[lane];
                float2 f0 = __half22float2(*(const __half2*)&u.x);
                float2 f1 = __half22float2(*(const __half2*)&u.y);
                acc[0] += c * f0.x; acc[1] += c * f0.y;
                acc[2] += c * f1.x; acc[3] += c * f1.y;
            } else {
                uint32_t u = ((const uint32_t*)(Hm + (size_t)sc * D))[lane];
                float2 f0 = __half22float2(*(const __half2*)&u);
                acc[0] += c * f0.x; acc[1] += c * f0.y;
            }
        }
    }
#pragma unroll
    for (int o = 16; o; o >>= 1)
        den += __shfl_xor_sync(0xFFFFFFFFu, den, o);
    float inv = 1.f / den;

    if (V == 4) {
        ((float4*)(out + (size_t)w * D))[lane] =
            make_float4(acc[0] * inv, acc[1] * inv, acc[2] * inv, acc[3] * inv);
    } else {
        ((float2*)(out + (size_t)w * D))[lane] =
            make_float2(acc[0] * inv, acc[1] * inv);
    }
}

// ---------------------------- BatchNorm ----------------------------------
template <int D>
__global__ void bn_stats_kernel(int n, const float* __restrict__ x,
                                float* __restrict__ stats) {
    int c = threadIdx.x;          // blockDim.x == D
    int r0 = blockIdx.x * 64;
    int r1 = min(r0 + 64, n);
    float s = 0.f, q = 0.f;
    for (int r = r0; r < r1; r++) {
        float v = x[(size_t)r * D + c];
        s += v;
        q += v * v;
    }
    atomicAdd(&stats[c], s);
    atomicAdd(&stats[128 + c], q);
}

template <int D>
__global__ void bn_finalize_kernel(int n, const float* __restrict__ stats,
                                   const float* __restrict__ g,
                                   const float* __restrict__ b,
                                   float* __restrict__ scale,
                                   float* __restrict__ shift) {
    int c = threadIdx.x;
    if (c >= D) return;
    float invn = 1.f / (float)n;
    float mu = stats[c] * invn;
    float var = stats[128 + c] * invn - mu * mu;
    float sc = g[c] * rsqrtf(var + EPS);
    scale[c] = sc;
    shift[c] = b[c] - mu * sc;
}

template <int D>
__global__ void bn_apply_kernel(int n, float* __restrict__ x,
                                const float* __restrict__ scale,
                                const float* __restrict__ shift) {
    int i = blockIdx.x * blockDim.x + threadIdx.x;
    if (i >= n * D) return;
    int c = i % D;
    x[i] = fmaxf(x[i] * scale[c] + shift[c], 0.f);
}

// ------------------------------ launcher ---------------------------------
extern "C" void kernel_launch(void* const* d_in, const int* in_sizes, int n_in,
                              void* d_out, int out_size) {
    const float* x   = (const float*)d_in[0];
    const int*   ei  = (const int*)d_in[1];
    const float* W0  = (const float*)d_in[2];
    const float* as0 = (const float*)d_in[3];
    const float* ad0 = (const float*)d_in[4];
    const float* gg0 = (const float*)d_in[5];
    const float* bb0 = (const float*)d_in[6];
    const float* W1  = (const float*)d_in[7];
    const float* as1 = (const float*)d_in[8];
    const float* ad1 = (const float*)d_in[9];
    const float* gg1 = (const float*)d_in[10];
    const float* bb1 = (const float*)d_in[11];

    const int F = 128, Hd = 128, C = 64;
    const int n  = in_sizes[0] / F;
    const int E_ = in_sizes[1] / 2;
    const int tot = E_ + n;
    float* out = (float*)d_out;

    float *abuf, *sbuf, *dbuf, *statb, *scaleb, *shiftb;
    __half* hbuf;
    int *degb, *rowp, *curs, *csrc, *bsums;
    cudaGetSymbolAddress((void**)&hbuf, g_h);
    cudaGetSymbolAddress((void**)&abuf, g_agg);
    cudaGetSymbolAddress((void**)&sbuf, g_s);
    cudaGetSymbolAddress((void**)&dbuf, g_d);
    cudaGetSymbolAddress((void**)&statb, g_stats);
    cudaGetSymbolAddress((void**)&scaleb, g_scale);
    cudaGetSymbolAddress((void**)&shiftb, g_shift);
    cudaGetSymbolAddress((void**)&degb, g_deg);
    cudaGetSymbolAddress((void**)&rowp, g_rowptr);
    cudaGetSymbolAddress((void**)&curs, g_cursor);
    cudaGetSymbolAddress((void**)&csrc, g_csrc);
    cudaGetSymbolAddress((void**)&bsums, g_bsums);

    // ======================= CSR build (shared by both layers) ============
    cudaMemsetAsync(degb, 0, (size_t)n * sizeof(int));
    hist_kernel<<<(tot + 255) / 256, 256>>>(E_, n, ei, degb);
    int nb = (n + 1023) / 1024;
    scan1_kernel<<<nb, 256>>>(degb, rowp, bsums, n);
    scan2_kernel<<<1, 32>>>(bsums, nb);
    scan3_kernel<<<(n + 255) / 256, 256>>>(rowp, curs, bsums, n, tot);
    fill_kernel<<<(tot + 255) / 256, 256>>>(E_, n, ei, curs, csrc);

    // ============================ Layer 0 =================================
    sgemm_fused_kernel<128, false><<<(n + 127) / 128, 256>>>(
        n, F, x, W0, hbuf, as0, ad0, sbuf, dbuf, nullptr, nullptr);
    gat_agg_kernel<128><<<(n * 32 + 255) / 256, 256>>>(n, rowp, csrc, sbuf, dbuf, hbuf, abuf);

    cudaMemsetAsync(statb, 0, 256 * sizeof(float));
    bn_stats_kernel<128><<<(n + 63) / 64, 128>>>(n, abuf, statb);
    bn_finalize_kernel<128><<<1, 128>>>(n, statb, gg0, bb0, scaleb, shiftb);

    // ============================ Layer 1 =================================
    sgemm_fused_kernel<64, true><<<(n + 127) / 128, 256>>>(
        n, Hd, abuf, W1, hbuf, as1, ad1, sbuf, dbuf, scaleb, shiftb);
    gat_agg_kernel<64><<<(n * 32 + 255) / 256, 256>>>(n, rowp, csrc, sbuf, dbuf, hbuf, out);

    cudaMemsetAsync(statb, 0, 256 * sizeof(float));
    bn_stats_kernel<64><<<(n + 63) / 64, 64>>>(n, out, statb);
    bn_finalize_kernel<64><<<1, 64>>>(n, statb, gg1, bb1, scaleb, shiftb);
    bn_apply_kernel<64><<<((long long)n * C + 255) / 256, 256>>>(n, out, scaleb, shiftb);
}

// round 8
// speedup vs baseline: 2.6810x; 1.0544x over previous
#include <cuda_runtime.h>
#include <cuda_fp16.h>
#include <cstdint>

#define NMAX 100000
#define EMAX 1700000
#define EPS 1e-5f

// -------- scratch (static device globals; no allocation allowed) --------
__device__ __half g_h[(size_t)NMAX * 128];   // GEMM output h in fp16
__device__ float g_agg[(size_t)NMAX * 128];  // layer-0 aggregation (pre-BN)
__device__ float g_s[NMAX];
__device__ float g_d[NMAX];
__device__ int   g_deg[NMAX];
__device__ int   g_rowptr[NMAX + 1];
__device__ int   g_cursor[NMAX];
__device__ int   g_csrc[EMAX];
__device__ int   g_bsums[256];
__device__ float g_stats[256];

// ---------------------- packed f32x2 helpers ------------------------------
__device__ __forceinline__ void fma2(uint64_t& d, uint64_t a, uint64_t b) {
    asm("fma.rn.f32x2 %0, %1, %2, %3;" : "=l"(d) : "l"(a), "l"(b), "l"(d));
}
__device__ __forceinline__ uint64_t dup2(float x) {
    uint64_t r;
    asm("mov.b64 %0, {%1, %1};" : "=l"(r) : "f"(x));
    return r;
}
__device__ __forceinline__ uint64_t pack2(float x, float y) {
    uint64_t r;
    asm("mov.b64 %0, {%1, %2};" : "=l"(r) : "f"(x), "f"(y));
    return r;
}
__device__ __forceinline__ float2 unpack2(uint64_t v) {
    float2 f;
    asm("mov.b64 {%0, %1}, %2;" : "=f"(f.x), "=f"(f.y) : "l"(v));
    return f;
}

// ------------------------------- SGEMM ----------------------------------
// C[M,N] (fp16) = A[M,K] @ B[K,N]; BN == N (one block column). If TRANSFORM,
// the BN scale/shift of the previous layer is computed in the prologue from
// raw column stats and applied (with ReLU) on the A-tile store. Fused per-row
// s = C·a_s, d = C·a_d (fp32). BM=128, BK=16, 256 threads, TM=8, TN=BN/16,
// packed FFMA2 inner product, register-prefetch double buffering.
template <int BN, bool TRANSFORM>
__global__ __launch_bounds__(256) void sgemm_fused_kernel(
    int M, int K,
    const float* __restrict__ A,
    const float* __restrict__ B,
    __half* __restrict__ C,
    const float* __restrict__ a_s,
    const float* __restrict__ a_d,
    float* __restrict__ so, float* __restrict__ dout,
    const float* __restrict__ stats,
    const float* __restrict__ gamma,
    const float* __restrict__ beta) {
    constexpr int BM = 128, BK = 16, TM = 8;
    constexpr int TN = BN / 16;
    constexpr int TP = TN / 2;
    constexpr int NA = 2;                 // A float4 regs per thread
    constexpr int NB = (BK * BN) / 1024;  // B float4 regs per thread (2 or 1)
    __shared__ float As[BK][BM];
    __shared__ float Bs[BK][BN];
    __shared__ float sscale[128], sshift[128];

    const int tid = threadIdx.x;
    const int tx = tid % 16;
    const int ty = tid / 16;
    const int rowBase = blockIdx.x * BM;

    uint64_t acc2[TM][TP];
#pragma unroll
    for (int i = 0; i < TM; i++)
#pragma unroll
        for (int j = 0; j < TP; j++) acc2[i][j] = 0ull;

    float asr[TN], adr[TN];
#pragma unroll
    for (int j = 0; j < TN; j++) {
        asr[j] = a_s[tx * TN + j];
        adr[j] = a_d[tx * TN + j];
    }

    float4 ra[NA], rb[NB];
    // prefetch tile 0
#pragma unroll
    for (int it = 0; it < NA; it++) {
        int idx = tid + it * 256;
        int r = idx >> 2, c4 = idx & 3;
        int gr = rowBase + r;
        ra[it] = (gr < M) ? *(const float4*)(A + (size_t)gr * K + c4 * 4)
                          : make_float4(0.f, 0.f, 0.f, 0.f);
    }
#pragma unroll
    for (int it = 0; it < NB; it++) {
        int idx = tid + it * 256;
        int kk = idx / (BN / 4), nv = idx % (BN / 4);
        rb[it] = *(const float4*)(B + (size_t)kk * BN + nv * 4);
    }

    if (TRANSFORM) {
        // compute BN scale/shift from raw stats (K <= 128)
        if (tid < K) {
            float invn = 1.f / (float)M;
            float mu = stats[tid] * invn;
            float var = stats[128 + tid] * invn - mu * mu;
            float sc = gamma[tid] * rsqrtf(var + EPS);
            sscale[tid] = sc;
            sshift[tid] = beta[tid] - mu * sc;
        }
        __syncthreads();
    }

    for (int k0 = 0; k0 < K; k0 += BK) {
        // ---- store prefetched tile to smem (A transposed, with transform) ----
#pragma unroll
        for (int it = 0; it < NA; it++) {
            int idx = tid + it * 256;
            int r = idx >> 2, c4 = idx & 3;
            float4 v = ra[it];
            int kk = c4 * 4;
            if (TRANSFORM) {
                v.x = fmaxf(v.x * sscale[k0 + kk + 0] + sshift[k0 + kk + 0], 0.f);
                v.y = fmaxf(v.y * sscale[k0 + kk + 1] + sshift[k0 + kk + 1], 0.f);
                v.z = fmaxf(v.z * sscale[k0 + kk + 2] + sshift[k0 + kk + 2], 0.f);
                v.w = fmaxf(v.w * sscale[k0 + kk + 3] + sshift[k0 + kk + 3], 0.f);
            }
            As[kk + 0][r] = v.x;
            As[kk + 1][r] = v.y;
            As[kk + 2][r] = v.z;
            As[kk + 3][r] = v.w;
        }
#pragma unroll
        for (int it = 0; it < NB; it++) {
            int idx = tid + it * 256;
            int kk = idx / (BN / 4), nv = idx % (BN / 4);
            *(float4*)&Bs[kk][nv * 4] = rb[it];
        }
        __syncthreads();
        // ---- prefetch next tile into regs ----
        if (k0 + BK < K) {
            int kn = k0 + BK;
#pragma unroll
            for (int it = 0; it < NA; it++) {
                int idx = tid + it * 256;
                int r = idx >> 2, c4 = idx & 3;
                int gr = rowBase + r;
                ra[it] = (gr < M) ? *(const float4*)(A + (size_t)gr * K + kn + c4 * 4)
                                  : make_float4(0.f, 0.f, 0.f, 0.f);
            }
#pragma unroll
            for (int it = 0; it < NB; it++) {
                int idx = tid + it * 256;
                int kk = idx / (BN / 4), nv = idx % (BN / 4);
                rb[it] = *(const float4*)(B + (size_t)(kn + kk) * BN + nv * 4);
            }
        }
        // ---- compute ----
#pragma unroll
        for (int kk = 0; kk < BK; kk++) {
            float4 a0 = *(const float4*)&As[kk][ty * TM];
            float4 a1 = *(const float4*)&As[kk][ty * TM + 4];
            uint64_t ad[TM];
            ad[0] = dup2(a0.x); ad[1] = dup2(a0.y);
            ad[2] = dup2(a0.z); ad[3] = dup2(a0.w);
            ad[4] = dup2(a1.x); ad[5] = dup2(a1.y);
            ad[6] = dup2(a1.z); ad[7] = dup2(a1.w);
            uint64_t b2[TP];
            const uint64_t* bp = (const uint64_t*)&Bs[kk][tx * TN];
#pragma unroll
            for (int j = 0; j < TP; j++) b2[j] = bp[j];
#pragma unroll
            for (int i = 0; i < TM; i++)
#pragma unroll
                for (int j = 0; j < TP; j++) fma2(acc2[i][j], ad[i], b2[j]);
        }
        __syncthreads();
    }

    // ---- epilogue: store fp16 C + fused per-row s,d dot products ----
#pragma unroll
    for (int i = 0; i < TM; i++) {
        int gr = rowBase + ty * TM + i;
        float vals[TN];
#pragma unroll
        for (int j = 0; j < TP; j++) {
            float2 f = unpack2(acc2[i][j]);
            vals[2 * j] = f.x;
            vals[2 * j + 1] = f.y;
        }
        float sp = 0.f, dp = 0.f;
#pragma unroll
        for (int j = 0; j < TN; j++) {
            sp += vals[j] * asr[j];
            dp += vals[j] * adr[j];
        }
        if (gr < M) {
            __half2 hv[TP];
#pragma unroll
            for (int j = 0; j < TP; j++)
                hv[j] = __floats2half2_rn(vals[2 * j], vals[2 * j + 1]);
            if (TP == 4)
                *(uint4*)(C + (size_t)gr * BN + tx * TN) = *(uint4*)hv;
            else
                *(uint2*)(C + (size_t)gr * BN + tx * TN) = *(uint2*)hv;
        }
#pragma unroll
        for (int off = 8; off; off >>= 1) {
            sp += __shfl_down_sync(0xFFFFFFFFu, sp, off, 16);
            dp += __shfl_down_sync(0xFFFFFFFFu, dp, off, 16);
        }
        if (tx == 0 && gr < M) { so[gr] = sp; dout[gr] = dp; }
    }
}

// ------------------------------ CSR build --------------------------------
__global__ void hist_kernel(int E_, int n, const int* __restrict__ ei,
                            int* __restrict__ deg) {
    int e = blockIdx.x * blockDim.x + threadIdx.x;
    int tot = E_ + n;
    if (e >= tot) return;
    int dst = (e < E_) ? ei[E_ + e] : (e - E_);
    atomicAdd(&deg[dst], 1);
}

__global__ void scan1_kernel(const int* __restrict__ deg, int* __restrict__ excl,
                             int* __restrict__ bsums, int n) {
    __shared__ int sh[256];
    int tid = threadIdx.x;
    int base = blockIdx.x * 1024 + tid * 4;
    int v[4];
#pragma unroll
    for (int j = 0; j < 4; j++) v[j] = (base + j < n) ? deg[base + j] : 0;
    int tsum = v[0] + v[1] + v[2] + v[3];
    sh[tid] = tsum;
    __syncthreads();
    for (int off = 1; off < 256; off <<= 1) {
        int t = (tid >= off) ? sh[tid - off] : 0;
        __syncthreads();
        sh[tid] += t;
        __syncthreads();
    }
    int run = sh[tid] - tsum;
#pragma unroll
    for (int j = 0; j < 4; j++) {
        if (base + j < n) excl[base + j] = run;
        run += v[j];
    }
    if (tid == 255) bsums[blockIdx.x] = sh[255];
}

__global__ void scan2_kernel(int* __restrict__ bsums, int nb) {
    if (threadIdx.x == 0 && blockIdx.x == 0) {
        int acc = 0;
        for (int i = 0; i < nb; i++) { int t = bsums[i]; bsums[i] = acc; acc += t; }
    }
}

__global__ void scan3_kernel(int* __restrict__ rowptr, int* __restrict__ cursor,
                             const int* __restrict__ bsums, int n, int tot) {
    int i = blockIdx.x * blockDim.x + threadIdx.x;
    if (i < n) {
        int v = rowptr[i] + bsums[i >> 10];
        rowptr[i] = v;
        cursor[i] = v;
    }
    if (i == 0) rowptr[n] = tot;
}

__global__ void fill_kernel(int E_, int n, const int* __restrict__ ei,
                            int* __restrict__ cursor, int* __restrict__ csrc) {
    int e = blockIdx.x * blockDim.x + threadIdx.x;
    int tot = E_ + n;
    if (e >= tot) return;
    int src, dst;
    if (e < E_) { src = ei[e]; dst = ei[E_ + e]; }
    else        { src = dst = e - E_; }
    int pos = atomicAdd(&cursor[dst], 1);
    csrc[pos] = src;
}

// ---------- single-pass per-dst softmax + feature aggregation ------------
// One warp per dst. Softmax is shift-invariant and logits bounded: no max
// pass. Packed f32x2 FMA accumulation.
template <int D>
__global__ void gat_agg_kernel(int n, const int* __restrict__ rowptr,
                               const int* __restrict__ csrc,
                               const float* __restrict__ s,
                               const float* __restrict__ dd,
                               const __half* __restrict__ Hm,
                               float* __restrict__ out) {
    constexpr int VP = D / 64;   // packed f32x2 accumulators per lane (2 or 1)
    int w = (blockIdx.x * blockDim.x + threadIdx.x) >> 5;
    int lane = threadIdx.x & 31;
    if (w >= n) return;
    int start = rowptr[w];
    int end = rowptr[w + 1];
    float dv = dd[w];

    float den = 0.f;
    uint64_t acc[VP];
#pragma unroll
    for (int j = 0; j < VP; j++) acc[j] = 0ull;

    for (int base = start; base < end; base += 32) {
        int i = base + lane;
        int srcv = 0;
        float wv = 0.f;
        if (i < end) {
            srcv = csrc[i];
            float lg = s[srcv] + dv;
            lg = lg > 0.f ? lg : 0.2f * lg;
            wv = __expf(lg);
        }
        den += wv;
        int cnt = min(32, end - base);
        for (int k = 0; k < cnt; k++) {
            float c = __shfl_sync(0xFFFFFFFFu, wv, k);
            int sc = __shfl_sync(0xFFFFFFFFu, srcv, k);
            uint64_t cd = dup2(c);
            if (VP == 2) {
                uint2 u = ((const uint2*)(Hm + (size_t)sc * D))[lane];
                float2 f0 = __half22float2(*(const __half2*)&u.x);
                float2 f1 = __half22float2(*(const __half2*)&u.y);
                fma2(acc[0], cd, pack2(f0.x, f0.y));
                fma2(acc[1], cd, pack2(f1.x, f1.y));
            } else {
                uint32_t u = ((const uint32_t*)(Hm + (size_t)sc * D))[lane];
                float2 f0 = __half22float2(*(const __half2*)&u);
                fma2(acc[0], cd, pack2(f0.x, f0.y));
            }
        }
    }
#pragma unroll
    for (int o = 16; o; o >>= 1)
        den += __shfl_xor_sync(0xFFFFFFFFu, den, o);
    float inv = 1.f / den;

    if (VP == 2) {
        float2 a0 = unpack2(acc[0]);
        float2 a1 = unpack2(acc[1]);
        ((float4*)(out + (size_t)w * D))[lane] =
            make_float4(a0.x * inv, a0.y * inv, a1.x * inv, a1.y * inv);
    } else {
        float2 a0 = unpack2(acc[0]);
        ((float2*)(out + (size_t)w * D))[lane] =
            make_float2(a0.x * inv, a0.y * inv);
    }
}

// ---------------------------- BatchNorm ----------------------------------
template <int D>
__global__ void bn_stats_kernel(int n, const float* __restrict__ x,
                                float* __restrict__ stats) {
    int c = threadIdx.x;          // blockDim.x == D
    int r0 = blockIdx.x * 64;
    int r1 = min(r0 + 64, n);
    float s = 0.f, q = 0.f;
    for (int r = r0; r < r1; r++) {
        float v = x[(size_t)r * D + c];
        s += v;
        q += v * v;
    }
    atomicAdd(&stats[c], s);
    atomicAdd(&stats[128 + c], q);
}

// scale/shift computed inline from raw stats (no finalize kernel)
template <int D>
__global__ void bn_apply_kernel(int n, float* __restrict__ x,
                                const float* __restrict__ stats,
                                const float* __restrict__ gamma,
                                const float* __restrict__ beta) {
    int i = blockIdx.x * blockDim.x + threadIdx.x;
    if (i >= n * D) return;
    int c = i % D;
    float invn = 1.f / (float)n;
    float mu = stats[c] * invn;
    float var = stats[128 + c] * invn - mu * mu;
    float sc = gamma[c] * rsqrtf(var + EPS);
    x[i] = fmaxf((x[i] - mu) * sc + beta[c], 0.f);
}

// ------------------------------ launcher ---------------------------------
extern "C" void kernel_launch(void* const* d_in, const int* in_sizes, int n_in,
                              void* d_out, int out_size) {
    const float* x   = (const float*)d_in[0];
    const int*   ei  = (const int*)d_in[1];
    const float* W0  = (const float*)d_in[2];
    const float* as0 = (const float*)d_in[3];
    const float* ad0 = (const float*)d_in[4];
    const float* gg0 = (const float*)d_in[5];
    const float* bb0 = (const float*)d_in[6];
    const float* W1  = (const float*)d_in[7];
    const float* as1 = (const float*)d_in[8];
    const float* ad1 = (const float*)d_in[9];
    const float* gg1 = (const float*)d_in[10];
    const float* bb1 = (const float*)d_in[11];

    const int F = 128, Hd = 128, C = 64;
    const int n  = in_sizes[0] / F;
    const int E_ = in_sizes[1] / 2;
    const int tot = E_ + n;
    float* out = (float*)d_out;

    float *abuf, *sbuf, *dbuf, *statb;
    __half* hbuf;
    int *degb, *rowp, *curs, *csrc, *bsums;
    cudaGetSymbolAddress((void**)&hbuf, g_h);
    cudaGetSymbolAddress((void**)&abuf, g_agg);
    cudaGetSymbolAddress((void**)&sbuf, g_s);
    cudaGetSymbolAddress((void**)&dbuf, g_d);
    cudaGetSymbolAddress((void**)&statb, g_stats);
    cudaGetSymbolAddress((void**)&degb, g_deg);
    cudaGetSymbolAddress((void**)&rowp, g_rowptr);
    cudaGetSymbolAddress((void**)&curs, g_cursor);
    cudaGetSymbolAddress((void**)&csrc, g_csrc);
    cudaGetSymbolAddress((void**)&bsums, g_bsums);

    // side stream + events, created once on the first (uncaptured) call.
    static cudaStream_t s2 = nullptr;
    static cudaEvent_t evFork = nullptr, evJoin = nullptr;
    if (s2 == nullptr) {
        cudaStreamCreateWithFlags(&s2, cudaStreamNonBlocking);
        cudaEventCreateWithFlags(&evFork, cudaEventDisableTiming);
        cudaEventCreateWithFlags(&evJoin, cudaEventDisableTiming);
    }

    // ============== fork: CSR build on s2, GEMM0 on default ===============
    cudaEventRecord(evFork, 0);
    cudaStreamWaitEvent(s2, evFork, 0);

    cudaMemsetAsync(degb, 0, (size_t)n * sizeof(int), s2);
    hist_kernel<<<(tot + 255) / 256, 256, 0, s2>>>(E_, n, ei, degb);
    int nb = (n + 1023) / 1024;
    scan1_kernel<<<nb, 256, 0, s2>>>(degb, rowp, bsums, n);
    scan2_kernel<<<1, 32, 0, s2>>>(bsums, nb);
    scan3_kernel<<<(n + 255) / 256, 256, 0, s2>>>(rowp, curs, bsums, n, tot);
    fill_kernel<<<(tot + 255) / 256, 256, 0, s2>>>(E_, n, ei, curs, csrc);
    cudaMemsetAsync(statb, 0, 256 * sizeof(float), s2);
    cudaEventRecord(evJoin, s2);

    // ============================ Layer 0 =================================
    sgemm_fused_kernel<128, false><<<(n + 127) / 128, 256>>>(
        n, F, x, W0, hbuf, as0, ad0, sbuf, dbuf, nullptr, nullptr, nullptr);

    cudaStreamWaitEvent(0, evJoin, 0);   // join: agg needs CSR
    gat_agg_kernel<128><<<(n * 32 + 255) / 256, 256>>>(n, rowp, csrc, sbuf, dbuf, hbuf, abuf);
    bn_stats_kernel<128><<<(n + 63) / 64, 128>>>(n, abuf, statb);

    // ============================ Layer 1 =================================
    // BN scale/shift computed inside the GEMM prologue from raw stats.
    sgemm_fused_kernel<64, true><<<(n + 127) / 128, 256>>>(
        n, Hd, abuf, W1, hbuf, as1, ad1, sbuf, dbuf, statb, gg0, bb0);
    cudaMemsetAsync(statb, 0, 256 * sizeof(float));   // after gemm1 (stream-ordered)
    gat_agg_kernel<64><<<(n * 32 + 255) / 256, 256>>>(n, rowp, csrc, sbuf, dbuf, hbuf, out);
    bn_stats_kernel<64><<<(n + 63) / 64, 64>>>(n, out, statb);
    bn_apply_kernel<64><<<((long long)n * C + 255) / 256, 256>>>(n, out, statb, gg1, bb1);
}